// round 3
// baseline (speedup 1.0000x reference)
#include <cuda_runtime.h>
#include <math.h>

// ---------------------------------------------------------------------------
// Problem constants
// ---------------------------------------------------------------------------
#define D_    1024
#define HD_   128
#define EA_   8
#define EF_   16
#define FH_   512
#define S_    1024
#define B_    4
#define NTOK_ 4096           // B*S
#define NTS_  8192           // NTOK*2 slots (top-2)
#define CAP_  4096           // max rows per expert

// ---------------------------------------------------------------------------
// Device-global scratch (allocation-free)
// ---------------------------------------------------------------------------
__device__ float g_xn  [NTOK_ * D_];
__device__ float g_xmid[NTOK_ * D_];
__device__ float g_xn2 [NTOK_ * D_];
__device__ float g_k   [NTOK_ * HD_];
__device__ float g_v   [NTOK_ * HD_];
__device__ float g_q   [NTS_  * HD_];
__device__ float g_ctx [NTS_  * HD_];
__device__ float g_ya  [NTS_  * D_];
__device__ float g_h   [NTS_  * FH_];
__device__ float g_yf  [NTS_  * D_];
__device__ float g_gwa [NTS_];
__device__ float g_gwf [NTS_];
__device__ int   g_cnt_a [EA_];
__device__ int   g_cnt_f [EF_];
__device__ int   g_list_a[EA_ * CAP_];
__device__ int   g_list_f[EF_ * CAP_];

// ---------------------------------------------------------------------------
// Zero routing counters (runs every launch)
// ---------------------------------------------------------------------------
__global__ void zero_k() {
    int t = threadIdx.x;
    if (t < EA_) g_cnt_a[t] = 0;
    if (t < EF_) g_cnt_f[t] = 0;
}

// ---------------------------------------------------------------------------
// LayerNorm: one block per token, 256 threads, float4 per thread
// ---------------------------------------------------------------------------
__global__ void __launch_bounds__(256) ln1_k(
    const float* __restrict__ x, const float* __restrict__ w,
    const float* __restrict__ b, float* __restrict__ y)
{
    int t = blockIdx.x, tid = threadIdx.x;
    float4 v = ((const float4*)(x + (size_t)t * D_))[tid];
    float s = v.x + v.y + v.z + v.w;
    float q = fmaf(v.x, v.x, fmaf(v.y, v.y, fmaf(v.z, v.z, v.w * v.w)));
    __shared__ float ss[8], sq[8];
    #pragma unroll
    for (int o = 16; o; o >>= 1) {
        s += __shfl_xor_sync(0xffffffffu, s, o);
        q += __shfl_xor_sync(0xffffffffu, q, o);
    }
    if ((tid & 31) == 0) { ss[tid >> 5] = s; sq[tid >> 5] = q; }
    __syncthreads();
    if (tid == 0) {
        float a = 0.f, c = 0.f;
        #pragma unroll
        for (int i = 0; i < 8; i++) { a += ss[i]; c += sq[i]; }
        ss[0] = a; sq[0] = c;
    }
    __syncthreads();
    float mu  = ss[0] * (1.f / D_);
    float var = sq[0] * (1.f / D_) - mu * mu;
    float rs  = rsqrtf(var + 1e-5f);
    float4 wv = ((const float4*)w)[tid];
    float4 bv = ((const float4*)b)[tid];
    float4 o;
    o.x = (v.x - mu) * rs * wv.x + bv.x;
    o.y = (v.y - mu) * rs * wv.y + bv.y;
    o.z = (v.z - mu) * rs * wv.z + bv.z;
    o.w = (v.w - mu) * rs * wv.w + bv.w;
    ((float4*)(y + (size_t)t * D_))[tid] = o;
}

// Residual-add of two slot rows + LayerNorm fused (writes xmid and xn2)
__global__ void __launch_bounds__(256) combine_ln2_k(
    const float* __restrict__ src, const float* __restrict__ ya,
    const float* __restrict__ w, const float* __restrict__ b,
    float* __restrict__ xmid, float* __restrict__ xn2)
{
    int t = blockIdx.x, tid = threadIdx.x;
    float4 v  = ((const float4*)(src + (size_t)t * D_))[tid];
    float4 y0 = ((const float4*)(ya + (size_t)(2 * t) * D_))[tid];
    float4 y1 = ((const float4*)(ya + (size_t)(2 * t + 1) * D_))[tid];
    v.x += y0.x + y1.x; v.y += y0.y + y1.y;
    v.z += y0.z + y1.z; v.w += y0.w + y1.w;
    ((float4*)(xmid + (size_t)t * D_))[tid] = v;

    float s = v.x + v.y + v.z + v.w;
    float q = fmaf(v.x, v.x, fmaf(v.y, v.y, fmaf(v.z, v.z, v.w * v.w)));
    __shared__ float ss[8], sq[8];
    #pragma unroll
    for (int o = 16; o; o >>= 1) {
        s += __shfl_xor_sync(0xffffffffu, s, o);
        q += __shfl_xor_sync(0xffffffffu, q, o);
    }
    if ((tid & 31) == 0) { ss[tid >> 5] = s; sq[tid >> 5] = q; }
    __syncthreads();
    if (tid == 0) {
        float a = 0.f, c = 0.f;
        #pragma unroll
        for (int i = 0; i < 8; i++) { a += ss[i]; c += sq[i]; }
        ss[0] = a; sq[0] = c;
    }
    __syncthreads();
    float mu  = ss[0] * (1.f / D_);
    float var = sq[0] * (1.f / D_) - mu * mu;
    float rs  = rsqrtf(var + 1e-5f);
    float4 wv = ((const float4*)w)[tid];
    float4 bv = ((const float4*)b)[tid];
    float4 o;
    o.x = (v.x - mu) * rs * wv.x + bv.x;
    o.y = (v.y - mu) * rs * wv.y + bv.y;
    o.z = (v.z - mu) * rs * wv.z + bv.z;
    o.w = (v.w - mu) * rs * wv.w + bv.w;
    ((float4*)(xn2 + (size_t)t * D_))[tid] = o;
}

// out = xmid + yf[2t] + yf[2t+1]
__global__ void __launch_bounds__(256) final_k(
    const float* __restrict__ xmid, const float* __restrict__ yf,
    float* __restrict__ out)
{
    int t = blockIdx.x, tid = threadIdx.x;
    float4 v  = ((const float4*)(xmid + (size_t)t * D_))[tid];
    float4 y0 = ((const float4*)(yf + (size_t)(2 * t) * D_))[tid];
    float4 y1 = ((const float4*)(yf + (size_t)(2 * t + 1) * D_))[tid];
    v.x += y0.x + y1.x; v.y += y0.y + y1.y;
    v.z += y0.z + y1.z; v.w += y0.w + y1.w;
    ((float4*)(out + (size_t)t * D_))[tid] = v;
}

// ---------------------------------------------------------------------------
// Routers: one warp per token. Top-2 + softmax gate, atomic list append.
// ---------------------------------------------------------------------------
__global__ void __launch_bounds__(256) route_attn_k(
    const float* __restrict__ xn, const float* __restrict__ gwm)
{
    int t = blockIdx.x * 8 + (threadIdx.x >> 5);
    int lane = threadIdx.x & 31;
    const float* x = xn + (size_t)t * D_;
    float acc[EA_];
    #pragma unroll
    for (int e = 0; e < EA_; e++) acc[e] = 0.f;
    for (int d = lane; d < D_; d += 32) {
        float xv = x[d];
        const float4* g4 = (const float4*)(gwm + (size_t)d * EA_);
        float4 ga = g4[0], gb = g4[1];
        acc[0] = fmaf(xv, ga.x, acc[0]); acc[1] = fmaf(xv, ga.y, acc[1]);
        acc[2] = fmaf(xv, ga.z, acc[2]); acc[3] = fmaf(xv, ga.w, acc[3]);
        acc[4] = fmaf(xv, gb.x, acc[4]); acc[5] = fmaf(xv, gb.y, acc[5]);
        acc[6] = fmaf(xv, gb.z, acc[6]); acc[7] = fmaf(xv, gb.w, acc[7]);
    }
    #pragma unroll
    for (int e = 0; e < EA_; e++)
        #pragma unroll
        for (int o = 16; o; o >>= 1)
            acc[e] += __shfl_xor_sync(0xffffffffu, acc[e], o);
    if (lane == 0) {
        int i0 = 0; float v0 = acc[0];
        #pragma unroll
        for (int e = 1; e < EA_; e++) if (acc[e] > v0) { v0 = acc[e]; i0 = e; }
        int i1 = -1; float v1 = -1e30f;
        #pragma unroll
        for (int e = 0; e < EA_; e++)
            if (e != i0 && acc[e] > v1) { v1 = acc[e]; i1 = e; }
        float e1 = __expf(v1 - v0);
        float inv = 1.f / (1.f + e1);
        g_gwa[2 * t]     = inv;
        g_gwa[2 * t + 1] = e1 * inv;
        int p0 = atomicAdd(&g_cnt_a[i0], 1);
        g_list_a[i0 * CAP_ + p0] = 2 * t;
        int p1 = atomicAdd(&g_cnt_a[i1], 1);
        g_list_a[i1 * CAP_ + p1] = 2 * t + 1;
    }
}

__global__ void __launch_bounds__(256) route_ffn_k(
    const float* __restrict__ xn, const float* __restrict__ gwm)
{
    int t = blockIdx.x * 8 + (threadIdx.x >> 5);
    int lane = threadIdx.x & 31;
    const float* x = xn + (size_t)t * D_;
    float acc[EF_];
    #pragma unroll
    for (int e = 0; e < EF_; e++) acc[e] = 0.f;
    for (int d = lane; d < D_; d += 32) {
        float xv = x[d];
        const float4* g4 = (const float4*)(gwm + (size_t)d * EF_);
        #pragma unroll
        for (int g = 0; g < 4; g++) {
            float4 gv = g4[g];
            acc[g*4+0] = fmaf(xv, gv.x, acc[g*4+0]);
            acc[g*4+1] = fmaf(xv, gv.y, acc[g*4+1]);
            acc[g*4+2] = fmaf(xv, gv.z, acc[g*4+2]);
            acc[g*4+3] = fmaf(xv, gv.w, acc[g*4+3]);
        }
    }
    #pragma unroll
    for (int e = 0; e < EF_; e++)
        #pragma unroll
        for (int o = 16; o; o >>= 1)
            acc[e] += __shfl_xor_sync(0xffffffffu, acc[e], o);
    if (lane == 0) {
        int i0 = 0; float v0 = acc[0];
        #pragma unroll
        for (int e = 1; e < EF_; e++) if (acc[e] > v0) { v0 = acc[e]; i0 = e; }
        int i1 = -1; float v1 = -1e30f;
        #pragma unroll
        for (int e = 0; e < EF_; e++)
            if (e != i0 && acc[e] > v1) { v1 = acc[e]; i1 = e; }
        float e1 = __expf(v1 - v0);
        float inv = 1.f / (1.f + e1);
        g_gwf[2 * t]     = inv;
        g_gwf[2 * t + 1] = e1 * inv;
        int p0 = atomicAdd(&g_cnt_f[i0], 1);
        g_list_f[i0 * CAP_ + p0] = 2 * t;
        int p1 = atomicAdd(&g_cnt_f[i1], 1);
        g_list_f[i1 * CAP_ + p1] = 2 * t + 1;
    }
}

// ---------------------------------------------------------------------------
// Grouped/gather GEMM: Y[slot] = f( X[row(slot)] @ W[e] + bias[e] )
// MODE 0: dense (row = r, slot = r)    MODE 1: row = list[r]>>1 (token)
// MODE 2: row = list[r] (slot)
// BM=128, BN=64, BK=16, 256 threads, 8x4 per-thread tile.
// ---------------------------------------------------------------------------
template<int MODE, bool RELU, bool GATE>
__global__ void __launch_bounds__(256) gemm_k(
    const float* __restrict__ X, int ldx,
    const float* __restrict__ Wb, const float* __restrict__ Bb,
    float* __restrict__ Y, int ldy,
    const int* __restrict__ lists, const int* __restrict__ cnts,
    const float* __restrict__ gw,
    int N, int K, int denseCnt, float scale)
{
    int e = blockIdx.z;
    int cnt = (MODE == 0) ? denseCnt : cnts[e];
    int row0 = blockIdx.y * 128;
    if (row0 >= cnt) return;
    const float* W = Wb + (size_t)e * K * N;
    const float* bias = Bb + (size_t)e * N;
    const int* list = (MODE == 0) ? nullptr : (lists + e * CAP_);
    int n0 = blockIdx.x * 64;

    __shared__ float As[16 * 132];
    __shared__ float Bs[16 * 68];

    int tid = threadIdx.x;
    int a_c4 = tid & 3;          // k-subgroup (4 floats)
    int a_r  = tid >> 2;         // row 0..63 (and +64)
    int r0i = row0 + a_r, r1i = row0 + 64 + a_r;
    int l0 = min(r0i, cnt - 1), l1 = min(r1i, cnt - 1);
    int sl0, sl1;
    if (MODE == 0) { sl0 = l0; sl1 = l1; }
    else           { sl0 = list[l0]; sl1 = list[l1]; }
    int gr0 = (MODE == 1) ? (sl0 >> 1) : sl0;
    int gr1 = (MODE == 1) ? (sl1 >> 1) : sl1;
    const float* Xr0 = X + (size_t)gr0 * ldx + a_c4 * 4;
    const float* Xr1 = X + (size_t)gr1 * ldx + a_c4 * 4;

    int b_r = tid >> 4;            // 0..15 (k row)
    int b_c = (tid & 15) * 4;      // 0..60 (n col)
    const float* Wp = W + (size_t)b_r * N + n0 + b_c;

    int m0  = (tid >> 4) * 8;
    int nn0 = (tid & 15) * 4;

    float acc[8][4];
    #pragma unroll
    for (int i = 0; i < 8; i++)
        #pragma unroll
        for (int j = 0; j < 4; j++) acc[i][j] = 0.f;

    for (int k0 = 0; k0 < K; k0 += 16) {
        float4 a0 = *(const float4*)(Xr0 + k0);
        float4 a1 = *(const float4*)(Xr1 + k0);
        float4 bv = *(const float4*)(Wp + (size_t)k0 * N);
        __syncthreads();
        As[(a_c4 * 4 + 0) * 132 + a_r] = a0.x;
        As[(a_c4 * 4 + 1) * 132 + a_r] = a0.y;
        As[(a_c4 * 4 + 2) * 132 + a_r] = a0.z;
        As[(a_c4 * 4 + 3) * 132 + a_r] = a0.w;
        As[(a_c4 * 4 + 0) * 132 + 64 + a_r] = a1.x;
        As[(a_c4 * 4 + 1) * 132 + 64 + a_r] = a1.y;
        As[(a_c4 * 4 + 2) * 132 + 64 + a_r] = a1.z;
        As[(a_c4 * 4 + 3) * 132 + 64 + a_r] = a1.w;
        *(float4*)&Bs[b_r * 68 + b_c] = bv;
        __syncthreads();
        #pragma unroll
        for (int kk = 0; kk < 16; kk++) {
            float4 av0 = *(const float4*)&As[kk * 132 + m0];
            float4 av1 = *(const float4*)&As[kk * 132 + m0 + 4];
            float4 bw  = *(const float4*)&Bs[kk * 68 + nn0];
            float af[8] = {av0.x, av0.y, av0.z, av0.w, av1.x, av1.y, av1.z, av1.w};
            float bf[4] = {bw.x, bw.y, bw.z, bw.w};
            #pragma unroll
            for (int i = 0; i < 8; i++)
                #pragma unroll
                for (int j = 0; j < 4; j++)
                    acc[i][j] = fmaf(af[i], bf[j], acc[i][j]);
        }
    }

    float4 bb = *(const float4*)(bias + n0 + nn0);
    float bias4[4] = {bb.x, bb.y, bb.z, bb.w};
    #pragma unroll
    for (int i = 0; i < 8; i++) {
        int r = row0 + m0 + i;
        if (r >= cnt) break;
        int slot = (MODE == 0) ? r : list[r];
        float f = scale;
        if (GATE) f *= gw[slot];
        float4 o;
        float t0 = acc[i][0] + bias4[0];
        float t1 = acc[i][1] + bias4[1];
        float t2 = acc[i][2] + bias4[2];
        float t3 = acc[i][3] + bias4[3];
        if (RELU) {
            t0 = fmaxf(t0, 0.f); t1 = fmaxf(t1, 0.f);
            t2 = fmaxf(t2, 0.f); t3 = fmaxf(t3, 0.f);
        }
        o.x = t0 * f; o.y = t1 * f; o.z = t2 * f; o.w = t3 * f;
        *(float4*)(Y + (size_t)slot * ldy + n0 + nn0) = o;
    }
}

// ---------------------------------------------------------------------------
// Attention: block = 16 slots (same batch), flash-style over 16 key tiles of 64
// dyn smem: Qs[16][132] Rl[16][132] Sb[16][68] state[64] Big{Kt[128][68]+Vs[64][132] | RelT[128][132]}
// ---------------------------------------------------------------------------
#define ATT_SMEM_FLOATS (2112 + 2112 + 1088 + 64 + 17152)
#define ATT_SMEM_BYTES  (ATT_SMEM_FLOATS * 4)

__global__ void __launch_bounds__(256) attn_k(
    const float* __restrict__ qg, const float* __restrict__ kg,
    const float* __restrict__ vg, const float* __restrict__ rel,
    float* __restrict__ ctxg)
{
    extern __shared__ float sm[];
    float* Qs  = sm;              // [16][132]
    float* Rl  = sm + 2112;       // [16][132]
    float* Sb  = sm + 4224;       // [16][68]
    float* Stm = sm + 5312;       // [16]
    float* Stl = Stm + 16;        // [16]
    float* Stc = Stm + 32;        // [16]
    float* Big = sm + 5376;
    float* Kt   = Big;            // [128][68]
    float* Vs   = Big + 8704;     // [64][132]
    float* RelT = Big;            // [128][132] (phase A only)

    int b = blockIdx.y;
    int qt = blockIdx.x;
    int slot_base = b * 2048 + qt * 16;
    int tid = threadIdx.x;

    // load Q rows (16 x 128)
    for (int i = tid; i < 512; i += 256) {
        int r = i >> 5, c = i & 31;
        float4 v = ((const float4*)(qg + (size_t)(slot_base + r) * HD_))[c];
        float* q = Qs + r * 132 + c * 4;
        q[0] = v.x; q[1] = v.y; q[2] = v.z; q[3] = v.w;
    }
    // load rel_table transposed (129 x 128 -> RelT[128][132])
    for (int i = tid; i < 129 * 32; i += 256) {
        int r = i >> 5, c = i & 31;
        float4 v = ((const float4*)(rel + (size_t)r * HD_))[c];
        RelT[(c * 4 + 0) * 132 + r] = v.x;
        RelT[(c * 4 + 1) * 132 + r] = v.y;
        RelT[(c * 4 + 2) * 132 + r] = v.z;
        RelT[(c * 4 + 3) * 132 + r] = v.w;
    }
    if (tid < 16) { Stm[tid] = -1e30f; Stl[tid] = 0.f; }
    __syncthreads();

    // rel scores: Rl[slot][r] = q[slot] . rel_table[r]
    for (int task = tid; task < 16 * 33; task += 256) {
        int slot = task / 33, rg = task % 33;
        const float* qrow = Qs + slot * 132;
        float a0 = 0, a1 = 0, a2 = 0, a3 = 0;
        #pragma unroll 8
        for (int kk = 0; kk < 128; kk++) {
            float qv = qrow[kk];
            float4 rv = *(const float4*)&RelT[kk * 132 + rg * 4];
            a0 = fmaf(qv, rv.x, a0); a1 = fmaf(qv, rv.y, a1);
            a2 = fmaf(qv, rv.z, a2); a3 = fmaf(qv, rv.w, a3);
        }
        float* o = Rl + slot * 132 + rg * 4;
        o[0] = a0; o[1] = a1; o[2] = a2; o[3] = a3;
    }

    int sc_slot = tid >> 4;
    int sc_jg   = tid & 15;
    int s_q = (qt * 16 + sc_slot) >> 1;     // query position in sequence
    int sp  = tid >> 5;                     // slot pair for ctx phase
    int d0  = (tid & 31) * 4;               // 4 dims per thread
    float acc[2][4] = {{0, 0, 0, 0}, {0, 0, 0, 0}};

    for (int kt = 0; kt < 16; kt++) {
        int j0 = kt * 64;
        __syncthreads();
        // load K tile transposed + V tile
        for (int i = tid; i < 64 * 32; i += 256) {
            int j = i >> 5, c = i & 31;
            float4 kv = ((const float4*)(kg + (size_t)(b * S_ + j0 + j) * HD_))[c];
            Kt[(c * 4 + 0) * 68 + j] = kv.x;
            Kt[(c * 4 + 1) * 68 + j] = kv.y;
            Kt[(c * 4 + 2) * 68 + j] = kv.z;
            Kt[(c * 4 + 3) * 68 + j] = kv.w;
            float4 vv = ((const float4*)(vg + (size_t)(b * S_ + j0 + j) * HD_))[c];
            *(float4*)&Vs[j * 132 + c * 4] = vv;
        }
        __syncthreads();
        // scores: 4 keys per thread
        float s[4] = {0, 0, 0, 0};
        {
            const float* qrow = Qs + sc_slot * 132;
            #pragma unroll 8
            for (int kk = 0; kk < 128; kk++) {
                float qv = qrow[kk];
                float4 kv = *(const float4*)&Kt[kk * 68 + sc_jg * 4];
                s[0] = fmaf(qv, kv.x, s[0]); s[1] = fmaf(qv, kv.y, s[1]);
                s[2] = fmaf(qv, kv.z, s[2]); s[3] = fmaf(qv, kv.w, s[3]);
            }
        }
        #pragma unroll
        for (int u = 0; u < 4; u++) {
            int j = j0 + sc_jg * 4 + u;
            int rr = j - s_q;
            rr = max(-64, min(64, rr)) + 64;
            s[u] += Rl[sc_slot * 132 + rr];
        }
        // online softmax within 16-thread groups
        float mx = fmaxf(fmaxf(s[0], s[1]), fmaxf(s[2], s[3]));
        #pragma unroll
        for (int o = 8; o; o >>= 1)
            mx = fmaxf(mx, __shfl_xor_sync(0xffffffffu, mx, o));
        float m_old = Stm[sc_slot];
        float m_new = fmaxf(m_old, mx);
        float ps = 0.f;
        #pragma unroll
        for (int u = 0; u < 4; u++) { s[u] = __expf(s[u] - m_new); ps += s[u]; }
        #pragma unroll
        for (int o = 8; o; o >>= 1)
            ps += __shfl_xor_sync(0xffffffffu, ps, o);
        *(float4*)&Sb[sc_slot * 68 + sc_jg * 4] = make_float4(s[0], s[1], s[2], s[3]);
        if ((tid & 15) == 0) {
            float scl = __expf(m_old - m_new);
            Stc[sc_slot] = scl;
            Stl[sc_slot] = Stl[sc_slot] * scl + ps;
            Stm[sc_slot] = m_new;
        }
        __syncthreads();
        // ctx accumulate: 2 slots x 4 dims per thread
        float sc0 = Stc[sp * 2], sc1 = Stc[sp * 2 + 1];
        #pragma unroll
        for (int u = 0; u < 4; u++) { acc[0][u] *= sc0; acc[1][u] *= sc1; }
        const float* p0r = Sb + (sp * 2) * 68;
        const float* p1r = Sb + (sp * 2 + 1) * 68;
        #pragma unroll 4
        for (int j = 0; j < 64; j++) {
            float p0 = p0r[j], p1 = p1r[j];
            float4 vv = *(const float4*)&Vs[j * 132 + d0];
            acc[0][0] = fmaf(p0, vv.x, acc[0][0]); acc[0][1] = fmaf(p0, vv.y, acc[0][1]);
            acc[0][2] = fmaf(p0, vv.z, acc[0][2]); acc[0][3] = fmaf(p0, vv.w, acc[0][3]);
            acc[1][0] = fmaf(p1, vv.x, acc[1][0]); acc[1][1] = fmaf(p1, vv.y, acc[1][1]);
            acc[1][2] = fmaf(p1, vv.z, acc[1][2]); acc[1][3] = fmaf(p1, vv.w, acc[1][3]);
        }
    }
    // normalize and write ctx
    float inv0 = 1.f / Stl[sp * 2];
    float inv1 = 1.f / Stl[sp * 2 + 1];
    float4 o0 = make_float4(acc[0][0] * inv0, acc[0][1] * inv0,
                            acc[0][2] * inv0, acc[0][3] * inv0);
    float4 o1 = make_float4(acc[1][0] * inv1, acc[1][1] * inv1,
                            acc[1][2] * inv1, acc[1][3] * inv1);
    *(float4*)(ctxg + (size_t)(slot_base + sp * 2) * HD_ + d0) = o0;
    *(float4*)(ctxg + (size_t)(slot_base + sp * 2 + 1) * HD_ + d0) = o1;
}

// ---------------------------------------------------------------------------
// Host launcher
// ---------------------------------------------------------------------------
extern "C" void kernel_launch(void* const* d_in, const int* in_sizes, int n_in,
                              void* d_out, int out_size) {
    const float* src  = (const float*)d_in[0];
    const float* ln1w = (const float*)d_in[1];
    const float* ln1b = (const float*)d_in[2];
    const float* ln2w = (const float*)d_in[3];
    const float* ln2b = (const float*)d_in[4];
    const float* agw  = (const float*)d_in[5];
    const float* qw   = (const float*)d_in[6];
    const float* qb   = (const float*)d_in[7];
    const float* kw   = (const float*)d_in[8];
    const float* kb   = (const float*)d_in[9];
    const float* vw   = (const float*)d_in[10];
    const float* vb   = (const float*)d_in[11];
    const float* ow   = (const float*)d_in[12];
    const float* ob   = (const float*)d_in[13];
    const float* rel  = (const float*)d_in[14];
    const float* fgw  = (const float*)d_in[15];
    const float* w1   = (const float*)d_in[16];
    const float* b1   = (const float*)d_in[17];
    const float* w2   = (const float*)d_in[18];
    const float* b2   = (const float*)d_in[19];
    float* out = (float*)d_out;

    float *xn, *xmid, *xn2, *kp, *vp, *qp, *ctx, *ya, *hh, *yf, *gwa, *gwf;
    int *cnta, *cntf, *lista, *listf;
    cudaGetSymbolAddress((void**)&xn,    g_xn);
    cudaGetSymbolAddress((void**)&xmid,  g_xmid);
    cudaGetSymbolAddress((void**)&xn2,   g_xn2);
    cudaGetSymbolAddress((void**)&kp,    g_k);
    cudaGetSymbolAddress((void**)&vp,    g_v);
    cudaGetSymbolAddress((void**)&qp,    g_q);
    cudaGetSymbolAddress((void**)&ctx,   g_ctx);
    cudaGetSymbolAddress((void**)&ya,    g_ya);
    cudaGetSymbolAddress((void**)&hh,    g_h);
    cudaGetSymbolAddress((void**)&yf,    g_yf);
    cudaGetSymbolAddress((void**)&gwa,   g_gwa);
    cudaGetSymbolAddress((void**)&gwf,   g_gwf);
    cudaGetSymbolAddress((void**)&cnta,  g_cnt_a);
    cudaGetSymbolAddress((void**)&cntf,  g_cnt_f);
    cudaGetSymbolAddress((void**)&lista, g_list_a);
    cudaGetSymbolAddress((void**)&listf, g_list_f);

    static bool attr_set = []() {
        cudaFuncSetAttribute(attn_k, cudaFuncAttributeMaxDynamicSharedMemorySize,
                             ATT_SMEM_BYTES);
        return true;
    }();
    (void)attr_set;

    zero_k<<<1, 32>>>();
    ln1_k<<<NTOK_, 256>>>(src, ln1w, ln1b, xn);

    // shared k/v projections (dense)
    dim3 gkv(HD_ / 64, NTOK_ / 128, 1);
    gemm_k<0, false, false><<<gkv, 256>>>(xn, D_, kw, kb, kp, HD_,
                                          nullptr, nullptr, nullptr,
                                          HD_, D_, NTOK_, 1.f);
    gemm_k<0, false, false><<<gkv, 256>>>(xn, D_, vw, vb, vp, HD_,
                                          nullptr, nullptr, nullptr,
                                          HD_, D_, NTOK_, 1.f);

    route_attn_k<<<NTOK_ / 8, 256>>>(xn, agw);

    // per-expert Q projection (gathered), q scaled by HD^-0.5
    dim3 gq(HD_ / 64, CAP_ / 128, EA_);
    gemm_k<1, false, false><<<gq, 256>>>(xn, D_, qw, qb, qp, HD_,
                                         lista, cnta, nullptr,
                                         HD_, D_, 0, 0.08838834764831845f);

    dim3 gat(128, B_);
    attn_k<<<gat, 256, ATT_SMEM_BYTES>>>(qp, kp, vp, rel, ctx);

    // per-expert output projection, gated
    dim3 go(D_ / 64, CAP_ / 128, EA_);
    gemm_k<2, false, true><<<go, 256>>>(ctx, HD_, ow, ob, ya, D_,
                                        lista, cnta, gwa,
                                        D_, HD_, 0, 1.f);

    combine_ln2_k<<<NTOK_, 256>>>(src, ya, ln2w, ln2b, xmid, xn2);
    route_ffn_k<<<NTOK_ / 8, 256>>>(xn2, fgw);

    dim3 g1(FH_ / 64, CAP_ / 128, EF_);
    gemm_k<1, true, false><<<g1, 256>>>(xn2, D_, w1, b1, hh, FH_,
                                        listf, cntf, nullptr,
                                        FH_, D_, 0, 1.f);
    dim3 g2(D_ / 64, CAP_ / 128, EF_);
    gemm_k<2, false, true><<<g2, 256>>>(hh, FH_, w2, b2, yf, D_,
                                        listf, cntf, gwf,
                                        D_, FH_, 0, 1.f);

    final_k<<<NTOK_, 256>>>(xmid, yf, out);
}

// round 5
// speedup vs baseline: 1.5139x; 1.5139x over previous
#include <cuda_runtime.h>
#include <cuda_bf16.h>
#include <math.h>
#include <stdint.h>

// ---------------------------------------------------------------------------
// Problem constants
// ---------------------------------------------------------------------------
#define D_    1024
#define HD_   128
#define EA_   8
#define EF_   16
#define FH_   512
#define S_    1024
#define B_    4
#define NTOK_ 4096           // B*S
#define NTS_  8192           // NTOK*2 slots (top-2)
#define CAP_  4096           // max rows per expert

// ---------------------------------------------------------------------------
// mma.sync helpers (baseline PTX, compiles for compute_103)
// ---------------------------------------------------------------------------
__device__ __forceinline__ uint32_t smem_to_u32(const void* p) {
    uint32_t a;
    asm("{ .reg .u64 t; cvta.to.shared.u64 t, %1; cvt.u32.u64 %0, t; }"
        : "=r"(a) : "l"(p));
    return a;
}
__device__ __forceinline__ void ldsm4(uint32_t& r0, uint32_t& r1,
                                      uint32_t& r2, uint32_t& r3, uint32_t a) {
    asm volatile("ldmatrix.sync.aligned.m8n8.x4.shared.b16 {%0,%1,%2,%3}, [%4];"
                 : "=r"(r0), "=r"(r1), "=r"(r2), "=r"(r3) : "r"(a));
}
__device__ __forceinline__ void mma16816(float* c, const uint32_t* a,
                                         const uint32_t* b) {
    asm volatile(
        "mma.sync.aligned.m16n8k16.row.col.f32.bf16.bf16.f32 "
        "{%0,%1,%2,%3}, {%4,%5,%6,%7}, {%8,%9}, {%0,%1,%2,%3};"
        : "+f"(c[0]), "+f"(c[1]), "+f"(c[2]), "+f"(c[3])
        : "r"(a[0]), "r"(a[1]), "r"(a[2]), "r"(a[3]), "r"(b[0]), "r"(b[1]));
}

// ---------------------------------------------------------------------------
// Device-global scratch (allocation-free)
// ---------------------------------------------------------------------------
__device__ float g_xn  [NTOK_ * D_];
__device__ float g_xmid[NTOK_ * D_];
__device__ float g_xn2 [NTOK_ * D_];
__device__ float g_k   [NTOK_ * HD_];
__device__ float g_v   [NTOK_ * HD_];
__device__ float g_q   [NTS_  * HD_];
__device__ float g_ctx [NTS_  * HD_];
__device__ float g_ya  [NTS_  * D_];
__device__ float g_yf  [NTS_  * D_];
__device__ float g_gwa [NTS_];
__device__ float g_gwf [NTS_];
__device__ int   g_cnt_a [EA_];
__device__ int   g_cnt_f [EF_];
__device__ int   g_list_a[EA_ * CAP_];
__device__ int   g_list_f[EF_ * CAP_];
// bf16 shadows for tensor-core FFN
__device__ __nv_bfloat16 g_xn2_bf[NTOK_ * D_];
__device__ __nv_bfloat16 g_h_bf  [NTS_  * FH_];
__device__ __nv_bfloat16 g_w1t   [EF_ * FH_ * D_];   // [e][n=FH][k=D]
__device__ __nv_bfloat16 g_w2t   [EF_ * D_ * FH_];   // [e][n=D][k=FH]

// ---------------------------------------------------------------------------
// Zero routing counters
// ---------------------------------------------------------------------------
__global__ void zero_k() {
    int t = threadIdx.x;
    if (t < EA_) g_cnt_a[t] = 0;
    if (t < EF_) g_cnt_f[t] = 0;
}

// ---------------------------------------------------------------------------
// Weight transpose + fp32->bf16 convert: W[E][K][N] -> O[E][N][K]
// ---------------------------------------------------------------------------
template<int K, int N>
__global__ void __launch_bounds__(256) convT_k(const float* __restrict__ W,
                                               __nv_bfloat16* __restrict__ O) {
    __shared__ float t[32][33];
    int e = blockIdx.z;
    int k0 = blockIdx.y * 32, n0 = blockIdx.x * 32;
    const float* w = W + (size_t)e * K * N;
    __nv_bfloat16* o = O + (size_t)e * N * K;
    int tx = threadIdx.x & 31, ty = threadIdx.x >> 5;
    #pragma unroll
    for (int i = 0; i < 32; i += 8)
        t[ty + i][tx] = w[(size_t)(k0 + ty + i) * N + n0 + tx];
    __syncthreads();
    #pragma unroll
    for (int i = 0; i < 32; i += 8)
        o[(size_t)(n0 + ty + i) * K + k0 + tx] = __float2bfloat16(t[tx][ty + i]);
}

// ---------------------------------------------------------------------------
// LayerNorm
// ---------------------------------------------------------------------------
__global__ void __launch_bounds__(256) ln1_k(
    const float* __restrict__ x, const float* __restrict__ w,
    const float* __restrict__ b, float* __restrict__ y)
{
    int t = blockIdx.x, tid = threadIdx.x;
    float4 v = ((const float4*)(x + (size_t)t * D_))[tid];
    float s = v.x + v.y + v.z + v.w;
    float q = fmaf(v.x, v.x, fmaf(v.y, v.y, fmaf(v.z, v.z, v.w * v.w)));
    __shared__ float ss[8], sq[8];
    #pragma unroll
    for (int o = 16; o; o >>= 1) {
        s += __shfl_xor_sync(0xffffffffu, s, o);
        q += __shfl_xor_sync(0xffffffffu, q, o);
    }
    if ((tid & 31) == 0) { ss[tid >> 5] = s; sq[tid >> 5] = q; }
    __syncthreads();
    if (tid == 0) {
        float a = 0.f, c = 0.f;
        #pragma unroll
        for (int i = 0; i < 8; i++) { a += ss[i]; c += sq[i]; }
        ss[0] = a; sq[0] = c;
    }
    __syncthreads();
    float mu  = ss[0] * (1.f / D_);
    float var = sq[0] * (1.f / D_) - mu * mu;
    float rs  = rsqrtf(var + 1e-5f);
    float4 wv = ((const float4*)w)[tid];
    float4 bv = ((const float4*)b)[tid];
    float4 o;
    o.x = (v.x - mu) * rs * wv.x + bv.x;
    o.y = (v.y - mu) * rs * wv.y + bv.y;
    o.z = (v.z - mu) * rs * wv.z + bv.z;
    o.w = (v.w - mu) * rs * wv.w + bv.w;
    ((float4*)(y + (size_t)t * D_))[tid] = o;
}

// Residual-add of two slot rows + LayerNorm fused (writes xmid, xn2 fp32 + bf16)
__global__ void __launch_bounds__(256) combine_ln2_k(
    const float* __restrict__ src, const float* __restrict__ ya,
    const float* __restrict__ w, const float* __restrict__ b,
    float* __restrict__ xmid, float* __restrict__ xn2,
    __nv_bfloat16* __restrict__ xn2bf)
{
    int t = blockIdx.x, tid = threadIdx.x;
    float4 v  = ((const float4*)(src + (size_t)t * D_))[tid];
    float4 y0 = ((const float4*)(ya + (size_t)(2 * t) * D_))[tid];
    float4 y1 = ((const float4*)(ya + (size_t)(2 * t + 1) * D_))[tid];
    v.x += y0.x + y1.x; v.y += y0.y + y1.y;
    v.z += y0.z + y1.z; v.w += y0.w + y1.w;
    ((float4*)(xmid + (size_t)t * D_))[tid] = v;

    float s = v.x + v.y + v.z + v.w;
    float q = fmaf(v.x, v.x, fmaf(v.y, v.y, fmaf(v.z, v.z, v.w * v.w)));
    __shared__ float ss[8], sq[8];
    #pragma unroll
    for (int o = 16; o; o >>= 1) {
        s += __shfl_xor_sync(0xffffffffu, s, o);
        q += __shfl_xor_sync(0xffffffffu, q, o);
    }
    if ((tid & 31) == 0) { ss[tid >> 5] = s; sq[tid >> 5] = q; }
    __syncthreads();
    if (tid == 0) {
        float a = 0.f, c = 0.f;
        #pragma unroll
        for (int i = 0; i < 8; i++) { a += ss[i]; c += sq[i]; }
        ss[0] = a; sq[0] = c;
    }
    __syncthreads();
    float mu  = ss[0] * (1.f / D_);
    float var = sq[0] * (1.f / D_) - mu * mu;
    float rs  = rsqrtf(var + 1e-5f);
    float4 wv = ((const float4*)w)[tid];
    float4 bv = ((const float4*)b)[tid];
    float4 o;
    o.x = (v.x - mu) * rs * wv.x + bv.x;
    o.y = (v.y - mu) * rs * wv.y + bv.y;
    o.z = (v.z - mu) * rs * wv.z + bv.z;
    o.w = (v.w - mu) * rs * wv.w + bv.w;
    ((float4*)(xn2 + (size_t)t * D_))[tid] = o;
    __nv_bfloat162 p0 = __floats2bfloat162_rn(o.x, o.y);
    __nv_bfloat162 p1 = __floats2bfloat162_rn(o.z, o.w);
    uint2 st;
    st.x = *(uint32_t*)&p0; st.y = *(uint32_t*)&p1;
    *(uint2*)(xn2bf + (size_t)t * D_ + tid * 4) = st;
}

// out = xmid + yf[2t] + yf[2t+1]
__global__ void __launch_bounds__(256) final_k(
    const float* __restrict__ xmid, const float* __restrict__ yf,
    float* __restrict__ out)
{
    int t = blockIdx.x, tid = threadIdx.x;
    float4 v  = ((const float4*)(xmid + (size_t)t * D_))[tid];
    float4 y0 = ((const float4*)(yf + (size_t)(2 * t) * D_))[tid];
    float4 y1 = ((const float4*)(yf + (size_t)(2 * t + 1) * D_))[tid];
    v.x += y0.x + y1.x; v.y += y0.y + y1.y;
    v.z += y0.z + y1.z; v.w += y0.w + y1.w;
    ((float4*)(out + (size_t)t * D_))[tid] = v;
}

// ---------------------------------------------------------------------------
// Routers (one warp per token, top-2, atomic list append)
// ---------------------------------------------------------------------------
__global__ void __launch_bounds__(256) route_attn_k(
    const float* __restrict__ xn, const float* __restrict__ gwm)
{
    int t = blockIdx.x * 8 + (threadIdx.x >> 5);
    int lane = threadIdx.x & 31;
    const float* x = xn + (size_t)t * D_;
    float acc[EA_];
    #pragma unroll
    for (int e = 0; e < EA_; e++) acc[e] = 0.f;
    for (int d = lane; d < D_; d += 32) {
        float xv = x[d];
        const float4* g4 = (const float4*)(gwm + (size_t)d * EA_);
        float4 ga = g4[0], gb = g4[1];
        acc[0] = fmaf(xv, ga.x, acc[0]); acc[1] = fmaf(xv, ga.y, acc[1]);
        acc[2] = fmaf(xv, ga.z, acc[2]); acc[3] = fmaf(xv, ga.w, acc[3]);
        acc[4] = fmaf(xv, gb.x, acc[4]); acc[5] = fmaf(xv, gb.y, acc[5]);
        acc[6] = fmaf(xv, gb.z, acc[6]); acc[7] = fmaf(xv, gb.w, acc[7]);
    }
    #pragma unroll
    for (int e = 0; e < EA_; e++)
        #pragma unroll
        for (int o = 16; o; o >>= 1)
            acc[e] += __shfl_xor_sync(0xffffffffu, acc[e], o);
    if (lane == 0) {
        int i0 = 0; float v0 = acc[0];
        #pragma unroll
        for (int e = 1; e < EA_; e++) if (acc[e] > v0) { v0 = acc[e]; i0 = e; }
        int i1 = -1; float v1 = -1e30f;
        #pragma unroll
        for (int e = 0; e < EA_; e++)
            if (e != i0 && acc[e] > v1) { v1 = acc[e]; i1 = e; }
        float e1 = __expf(v1 - v0);
        float inv = 1.f / (1.f + e1);
        g_gwa[2 * t]     = inv;
        g_gwa[2 * t + 1] = e1 * inv;
        int p0 = atomicAdd(&g_cnt_a[i0], 1);
        g_list_a[i0 * CAP_ + p0] = 2 * t;
        int p1 = atomicAdd(&g_cnt_a[i1], 1);
        g_list_a[i1 * CAP_ + p1] = 2 * t + 1;
    }
}

__global__ void __launch_bounds__(256) route_ffn_k(
    const float* __restrict__ xn, const float* __restrict__ gwm)
{
    int t = blockIdx.x * 8 + (threadIdx.x >> 5);
    int lane = threadIdx.x & 31;
    const float* x = xn + (size_t)t * D_;
    float acc[EF_];
    #pragma unroll
    for (int e = 0; e < EF_; e++) acc[e] = 0.f;
    for (int d = lane; d < D_; d += 32) {
        float xv = x[d];
        const float4* g4 = (const float4*)(gwm + (size_t)d * EF_);
        #pragma unroll
        for (int g = 0; g < 4; g++) {
            float4 gv = g4[g];
            acc[g*4+0] = fmaf(xv, gv.x, acc[g*4+0]);
            acc[g*4+1] = fmaf(xv, gv.y, acc[g*4+1]);
            acc[g*4+2] = fmaf(xv, gv.z, acc[g*4+2]);
            acc[g*4+3] = fmaf(xv, gv.w, acc[g*4+3]);
        }
    }
    #pragma unroll
    for (int e = 0; e < EF_; e++)
        #pragma unroll
        for (int o = 16; o; o >>= 1)
            acc[e] += __shfl_xor_sync(0xffffffffu, acc[e], o);
    if (lane == 0) {
        int i0 = 0; float v0 = acc[0];
        #pragma unroll
        for (int e = 1; e < EF_; e++) if (acc[e] > v0) { v0 = acc[e]; i0 = e; }
        int i1 = -1; float v1 = -1e30f;
        #pragma unroll
        for (int e = 0; e < EF_; e++)
            if (e != i0 && acc[e] > v1) { v1 = acc[e]; i1 = e; }
        float e1 = __expf(v1 - v0);
        float inv = 1.f / (1.f + e1);
        g_gwf[2 * t]     = inv;
        g_gwf[2 * t + 1] = e1 * inv;
        int p0 = atomicAdd(&g_cnt_f[i0], 1);
        g_list_f[i0 * CAP_ + p0] = 2 * t;
        int p1 = atomicAdd(&g_cnt_f[i1], 1);
        g_list_f[i1 * CAP_ + p1] = 2 * t + 1;
    }
}

// ---------------------------------------------------------------------------
// FP32 grouped/gather GEMM (kept for k/v, q, o projections)
// MODE 0: dense (z picks {W,B,Y} vs {W2,B2,Y2})  MODE 1: row=list[r]>>1  MODE 2: row=list[r]
// ---------------------------------------------------------------------------
template<int MODE, bool RELU, bool GATE>
__global__ void __launch_bounds__(256) gemm_k(
    const float* __restrict__ X, int ldx,
    const float* __restrict__ Wb, const float* __restrict__ Bb,
    float* __restrict__ Y, int ldy,
    const float* __restrict__ Wb2, const float* __restrict__ Bb2,
    float* __restrict__ Y2,
    const int* __restrict__ lists, const int* __restrict__ cnts,
    const float* __restrict__ gw,
    int N, int K, int denseCnt, float scale)
{
    int e = (MODE == 0) ? 0 : blockIdx.z;
    int cnt = (MODE == 0) ? denseCnt : cnts[e];
    int row0 = blockIdx.y * 128;
    if (row0 >= cnt) return;
    const float* W = Wb + (size_t)e * K * N;
    const float* bias = Bb + (size_t)e * N;
    float* Yp = Y;
    if (MODE == 0 && blockIdx.z == 1) { W = Wb2; bias = Bb2; Yp = Y2; }
    const int* list = (MODE == 0) ? nullptr : (lists + e * CAP_);
    int n0 = blockIdx.x * 64;

    __shared__ float As[16 * 132];
    __shared__ float Bs[16 * 68];

    int tid = threadIdx.x;
    int a_c4 = tid & 3;
    int a_r  = tid >> 2;
    int r0i = row0 + a_r, r1i = row0 + 64 + a_r;
    int l0 = min(r0i, cnt - 1), l1 = min(r1i, cnt - 1);
    int sl0, sl1;
    if (MODE == 0) { sl0 = l0; sl1 = l1; }
    else           { sl0 = list[l0]; sl1 = list[l1]; }
    int gr0 = (MODE == 1) ? (sl0 >> 1) : sl0;
    int gr1 = (MODE == 1) ? (sl1 >> 1) : sl1;
    const float* Xr0 = X + (size_t)gr0 * ldx + a_c4 * 4;
    const float* Xr1 = X + (size_t)gr1 * ldx + a_c4 * 4;

    int b_r = tid >> 4;
    int b_c = (tid & 15) * 4;
    const float* Wp = W + (size_t)b_r * N + n0 + b_c;

    int m0  = (tid >> 4) * 8;
    int nn0 = (tid & 15) * 4;

    float acc[8][4];
    #pragma unroll
    for (int i = 0; i < 8; i++)
        #pragma unroll
        for (int j = 0; j < 4; j++) acc[i][j] = 0.f;

    for (int k0 = 0; k0 < K; k0 += 16) {
        float4 a0 = *(const float4*)(Xr0 + k0);
        float4 a1 = *(const float4*)(Xr1 + k0);
        float4 bv = *(const float4*)(Wp + (size_t)k0 * N);
        __syncthreads();
        As[(a_c4 * 4 + 0) * 132 + a_r] = a0.x;
        As[(a_c4 * 4 + 1) * 132 + a_r] = a0.y;
        As[(a_c4 * 4 + 2) * 132 + a_r] = a0.z;
        As[(a_c4 * 4 + 3) * 132 + a_r] = a0.w;
        As[(a_c4 * 4 + 0) * 132 + 64 + a_r] = a1.x;
        As[(a_c4 * 4 + 1) * 132 + 64 + a_r] = a1.y;
        As[(a_c4 * 4 + 2) * 132 + 64 + a_r] = a1.z;
        As[(a_c4 * 4 + 3) * 132 + 64 + a_r] = a1.w;
        *(float4*)&Bs[b_r * 68 + b_c] = bv;
        __syncthreads();
        #pragma unroll
        for (int kk = 0; kk < 16; kk++) {
            float4 av0 = *(const float4*)&As[kk * 132 + m0];
            float4 av1 = *(const float4*)&As[kk * 132 + m0 + 4];
            float4 bw  = *(const float4*)&Bs[kk * 68 + nn0];
            float af[8] = {av0.x, av0.y, av0.z, av0.w, av1.x, av1.y, av1.z, av1.w};
            float bf[4] = {bw.x, bw.y, bw.z, bw.w};
            #pragma unroll
            for (int i = 0; i < 8; i++)
                #pragma unroll
                for (int j = 0; j < 4; j++)
                    acc[i][j] = fmaf(af[i], bf[j], acc[i][j]);
        }
    }

    float4 bb = *(const float4*)(bias + n0 + nn0);
    float bias4[4] = {bb.x, bb.y, bb.z, bb.w};
    #pragma unroll
    for (int i = 0; i < 8; i++) {
        int r = row0 + m0 + i;
        if (r >= cnt) break;
        int slot = (MODE == 0) ? r : list[r];
        float f = scale;
        if (GATE) f *= gw[slot];
        float4 o;
        float t0 = acc[i][0] + bias4[0];
        float t1 = acc[i][1] + bias4[1];
        float t2 = acc[i][2] + bias4[2];
        float t3 = acc[i][3] + bias4[3];
        if (RELU) {
            t0 = fmaxf(t0, 0.f); t1 = fmaxf(t1, 0.f);
            t2 = fmaxf(t2, 0.f); t3 = fmaxf(t3, 0.f);
        }
        o.x = t0 * f; o.y = t1 * f; o.z = t2 * f; o.w = t3 * f;
        *(float4*)(Yp + (size_t)slot * ldy + n0 + nn0) = o;
    }
}

// ---------------------------------------------------------------------------
// bf16 mma.sync grouped GEMM for the MoE FFN.
// BM=128, BN=128, BK=64. 8 warps in 4(M)x2(N); warp tile 32x64 = 2x8 HMMA.16816.
// A gathered by expert list; epilogue fuses bias/relu/gate; out bf16 or fp32.
// MODE 1: A row = list[r]>>1 (token rows);  MODE 2: A row = list[r] (slot rows)
// ---------------------------------------------------------------------------
#define LDAB 72   // bf16 elements per smem row (64 + 8 pad): 144B stride

template<int KTOT, int MODE, bool RELU, bool GATE, bool OUTBF>
__global__ void __launch_bounds__(256) mmasync_ffn_k(
    const __nv_bfloat16* __restrict__ Abase,
    const __nv_bfloat16* __restrict__ Bbase,
    const float* __restrict__ biasb, int Nfull,
    void* __restrict__ Yv, int ldy,
    const int* __restrict__ lists, const int* __restrict__ cnts,
    const float* __restrict__ gw)
{
    int e = blockIdx.z;
    int cnt = cnts[e];
    int row0 = blockIdx.y * 128;
    if (row0 >= cnt) return;
    int n0 = blockIdx.x * 128;
    const int* list = lists + e * CAP_;

    __shared__ __nv_bfloat16 As[128 * LDAB];
    __shared__ __nv_bfloat16 Bs[128 * LDAB];
    __shared__ float bias_s[128];
    __shared__ float gate_s[128];
    __shared__ int   slot_s[128];

    int tid = threadIdx.x;
    int wid = tid >> 5, lane = tid & 31;

    // Per-row maps
    if (tid < 128) {
        int r = min(row0 + tid, cnt - 1);
        int sl = list[r];
        slot_s[tid] = sl;
        gate_s[tid] = GATE ? gw[sl] : 1.f;
        bias_s[tid] = biasb[(size_t)e * Nfull + n0 + tid];
    }

    // Global load assignments: 4 uint4 chunks each for A and B
    const __nv_bfloat16* Bexp = Bbase + (size_t)e * Nfull * KTOT;
    const __nv_bfloat16* aSrc[4];
    const __nv_bfloat16* bSrc[4];
    uint32_t aDst[4], bDst[4];
    uint32_t sA = smem_to_u32(As), sB = smem_to_u32(Bs);
    #pragma unroll
    for (int i = 0; i < 4; i++) {
        int idx = tid + i * 256;
        int m = idx >> 3, c = idx & 7;
        int r = min(row0 + m, cnt - 1);
        int sl = list[r];
        int gr = (MODE == 1) ? (sl >> 1) : sl;
        aSrc[i] = Abase + (size_t)gr * KTOT + c * 8;
        bSrc[i] = Bexp + (size_t)(n0 + m) * KTOT + c * 8;
        aDst[i] = sA + (m * LDAB + c * 8) * 2;
        bDst[i] = sB + (m * LDAB + c * 8) * 2;
    }

    // ldmatrix base addresses
    int warpM = (wid & 3) * 32;
    int warpN = (wid >> 2) * 64;
    uint32_t aAddr = sA + ((warpM + (lane & 15)) * LDAB + (lane >> 4) * 8) * 2;
    uint32_t bAddr = sB + ((warpN + ((lane >> 4) & 1) * 8 + (lane & 7)) * LDAB
                           + ((lane >> 3) & 1) * 8) * 2;

    float acc[2][8][4];
    #pragma unroll
    for (int mt = 0; mt < 2; mt++)
        #pragma unroll
        for (int nt = 0; nt < 8; nt++)
            #pragma unroll
            for (int j = 0; j < 4; j++) acc[mt][nt][j] = 0.f;

    uint4 aR[4], bR[4];
    #pragma unroll
    for (int i = 0; i < 4; i++) {
        aR[i] = *(const uint4*)(aSrc[i]);
        bR[i] = *(const uint4*)(bSrc[i]);
    }

    const int NSTAGE = KTOT / 64;
    for (int st = 0; st < NSTAGE; st++) {
        __syncthreads();
        #pragma unroll
        for (int i = 0; i < 4; i++) {
            *(uint4*)(As + 0) = *(uint4*)(As + 0); // no-op barrier breaker removed by compiler
        }
        #pragma unroll
        for (int i = 0; i < 4; i++) {
            asm volatile("st.shared.v4.b32 [%0], {%1,%2,%3,%4};" ::
                "r"(aDst[i]), "r"(aR[i].x), "r"(aR[i].y), "r"(aR[i].z), "r"(aR[i].w));
            asm volatile("st.shared.v4.b32 [%0], {%1,%2,%3,%4};" ::
                "r"(bDst[i]), "r"(bR[i].x), "r"(bR[i].y), "r"(bR[i].z), "r"(bR[i].w));
        }
        __syncthreads();
        if (st + 1 < NSTAGE) {
            int k0 = (st + 1) * 64;
            #pragma unroll
            for (int i = 0; i < 4; i++) {
                aR[i] = *(const uint4*)(aSrc[i] + k0);
                bR[i] = *(const uint4*)(bSrc[i] + k0);
            }
        }
        #pragma unroll
        for (int kk = 0; kk < 4; kk++) {
            uint32_t a[2][4];
            ldsm4(a[0][0], a[0][1], a[0][2], a[0][3], aAddr + kk * 32);
            ldsm4(a[1][0], a[1][1], a[1][2], a[1][3],
                  aAddr + 16 * LDAB * 2 + kk * 32);
            uint32_t b[8][2];
            #pragma unroll
            for (int nt2 = 0; nt2 < 4; nt2++) {
                uint32_t r0, r1, r2, r3;
                ldsm4(r0, r1, r2, r3, bAddr + nt2 * 16 * LDAB * 2 + kk * 32);
                b[nt2 * 2][0] = r0;     b[nt2 * 2][1] = r1;
                b[nt2 * 2 + 1][0] = r2; b[nt2 * 2 + 1][1] = r3;
            }
            #pragma unroll
            for (int mt = 0; mt < 2; mt++)
                #pragma unroll
                for (int nt = 0; nt < 8; nt++)
                    mma16816(acc[mt][nt], a[mt], b[nt]);
        }
    }

    // Epilogue
    int lane4 = lane >> 2;
    int lcol  = (lane & 3) * 2;
    #pragma unroll
    for (int mt = 0; mt < 2; mt++) {
        #pragma unroll
        for (int h = 0; h < 2; h++) {
            int m = warpM + mt * 16 + lane4 + h * 8;
            if (row0 + m >= cnt) continue;
            int sl = slot_s[m];
            float f = gate_s[m];
            #pragma unroll
            for (int nt = 0; nt < 8; nt++) {
                int col = warpN + nt * 8 + lcol;
                float v0 = acc[mt][nt][h * 2 + 0] + bias_s[col];
                float v1 = acc[mt][nt][h * 2 + 1] + bias_s[col + 1];
                if (RELU) { v0 = fmaxf(v0, 0.f); v1 = fmaxf(v1, 0.f); }
                v0 *= f; v1 *= f;
                if (OUTBF) {
                    __nv_bfloat162 p = __floats2bfloat162_rn(v0, v1);
                    *(uint32_t*)((__nv_bfloat16*)Yv + (size_t)sl * ldy + n0 + col) =
                        *(uint32_t*)&p;
                } else {
                    float2 p = make_float2(v0, v1);
                    *(float2*)((float*)Yv + (size_t)sl * ldy + n0 + col) = p;
                }
            }
        }
    }
}

// ---------------------------------------------------------------------------
// Attention (unchanged)
// ---------------------------------------------------------------------------
#define ATT_SMEM_FLOATS (2112 + 2112 + 1088 + 64 + 17152)
#define ATT_SMEM_BYTES  (ATT_SMEM_FLOATS * 4)

__global__ void __launch_bounds__(256) attn_k(
    const float* __restrict__ qg, const float* __restrict__ kg,
    const float* __restrict__ vg, const float* __restrict__ rel,
    float* __restrict__ ctxg)
{
    extern __shared__ float smf[];
    float* Qs  = smf;
    float* Rl  = smf + 2112;
    float* Sb  = smf + 4224;
    float* Stm = smf + 5312;
    float* Stl = Stm + 16;
    float* Stc = Stm + 32;
    float* Big = smf + 5376;
    float* Kt   = Big;
    float* Vs   = Big + 8704;
    float* RelT = Big;

    int b = blockIdx.y;
    int qt = blockIdx.x;
    int slot_base = b * 2048 + qt * 16;
    int tid = threadIdx.x;

    for (int i = tid; i < 512; i += 256) {
        int r = i >> 5, c = i & 31;
        float4 v = ((const float4*)(qg + (size_t)(slot_base + r) * HD_))[c];
        float* q = Qs + r * 132 + c * 4;
        q[0] = v.x; q[1] = v.y; q[2] = v.z; q[3] = v.w;
    }
    for (int i = tid; i < 129 * 32; i += 256) {
        int r = i >> 5, c = i & 31;
        float4 v = ((const float4*)(rel + (size_t)r * HD_))[c];
        RelT[(c * 4 + 0) * 132 + r] = v.x;
        RelT[(c * 4 + 1) * 132 + r] = v.y;
        RelT[(c * 4 + 2) * 132 + r] = v.z;
        RelT[(c * 4 + 3) * 132 + r] = v.w;
    }
    if (tid < 16) { Stm[tid] = -1e30f; Stl[tid] = 0.f; }
    __syncthreads();

    for (int task = tid; task < 16 * 33; task += 256) {
        int slot = task / 33, rg = task % 33;
        const float* qrow = Qs + slot * 132;
        float a0 = 0, a1 = 0, a2 = 0, a3 = 0;
        #pragma unroll 8
        for (int kk = 0; kk < 128; kk++) {
            float qv = qrow[kk];
            float4 rv = *(const float4*)&RelT[kk * 132 + rg * 4];
            a0 = fmaf(qv, rv.x, a0); a1 = fmaf(qv, rv.y, a1);
            a2 = fmaf(qv, rv.z, a2); a3 = fmaf(qv, rv.w, a3);
        }
        float* o = Rl + slot * 132 + rg * 4;
        o[0] = a0; o[1] = a1; o[2] = a2; o[3] = a3;
    }

    int sc_slot = tid >> 4;
    int sc_jg   = tid & 15;
    int s_q = (qt * 16 + sc_slot) >> 1;
    int sp  = tid >> 5;
    int d0  = (tid & 31) * 4;
    float acc[2][4] = {{0, 0, 0, 0}, {0, 0, 0, 0}};

    for (int kt = 0; kt < 16; kt++) {
        int j0 = kt * 64;
        __syncthreads();
        for (int i = tid; i < 64 * 32; i += 256) {
            int j = i >> 5, c = i & 31;
            float4 kv = ((const float4*)(kg + (size_t)(b * S_ + j0 + j) * HD_))[c];
            Kt[(c * 4 + 0) * 68 + j] = kv.x;
            Kt[(c * 4 + 1) * 68 + j] = kv.y;
            Kt[(c * 4 + 2) * 68 + j] = kv.z;
            Kt[(c * 4 + 3) * 68 + j] = kv.w;
            float4 vv = ((const float4*)(vg + (size_t)(b * S_ + j0 + j) * HD_))[c];
            *(float4*)&Vs[j * 132 + c * 4] = vv;
        }
        __syncthreads();
        float s[4] = {0, 0, 0, 0};
        {
            const float* qrow = Qs + sc_slot * 132;
            #pragma unroll 8
            for (int kk = 0; kk < 128; kk++) {
                float qv = qrow[kk];
                float4 kv = *(const float4*)&Kt[kk * 68 + sc_jg * 4];
                s[0] = fmaf(qv, kv.x, s[0]); s[1] = fmaf(qv, kv.y, s[1]);
                s[2] = fmaf(qv, kv.z, s[2]); s[3] = fmaf(qv, kv.w, s[3]);
            }
        }
        #pragma unroll
        for (int u = 0; u < 4; u++) {
            int j = j0 + sc_jg * 4 + u;
            int rr = j - s_q;
            rr = max(-64, min(64, rr)) + 64;
            s[u] += Rl[sc_slot * 132 + rr];
        }
        float mx = fmaxf(fmaxf(s[0], s[1]), fmaxf(s[2], s[3]));
        #pragma unroll
        for (int o = 8; o; o >>= 1)
            mx = fmaxf(mx, __shfl_xor_sync(0xffffffffu, mx, o));
        float m_old = Stm[sc_slot];
        float m_new = fmaxf(m_old, mx);
        float ps = 0.f;
        #pragma unroll
        for (int u = 0; u < 4; u++) { s[u] = __expf(s[u] - m_new); ps += s[u]; }
        #pragma unroll
        for (int o = 8; o; o >>= 1)
            ps += __shfl_xor_sync(0xffffffffu, ps, o);
        *(float4*)&Sb[sc_slot * 68 + sc_jg * 4] = make_float4(s[0], s[1], s[2], s[3]);
        if ((tid & 15) == 0) {
            float scl = __expf(m_old - m_new);
            Stc[sc_slot] = scl;
            Stl[sc_slot] = Stl[sc_slot] * scl + ps;
            Stm[sc_slot] = m_new;
        }
        __syncthreads();
        float sc0 = Stc[sp * 2], sc1 = Stc[sp * 2 + 1];
        #pragma unroll
        for (int u = 0; u < 4; u++) { acc[0][u] *= sc0; acc[1][u] *= sc1; }
        const float* p0r = Sb + (sp * 2) * 68;
        const float* p1r = Sb + (sp * 2 + 1) * 68;
        #pragma unroll 4
        for (int j = 0; j < 64; j++) {
            float p0 = p0r[j], p1 = p1r[j];
            float4 vv = *(const float4*)&Vs[j * 132 + d0];
            acc[0][0] = fmaf(p0, vv.x, acc[0][0]); acc[0][1] = fmaf(p0, vv.y, acc[0][1]);
            acc[0][2] = fmaf(p0, vv.z, acc[0][2]); acc[0][3] = fmaf(p0, vv.w, acc[0][3]);
            acc[1][0] = fmaf(p1, vv.x, acc[1][0]); acc[1][1] = fmaf(p1, vv.y, acc[1][1]);
            acc[1][2] = fmaf(p1, vv.z, acc[1][2]); acc[1][3] = fmaf(p1, vv.w, acc[1][3]);
        }
    }
    float inv0 = 1.f / Stl[sp * 2];
    float inv1 = 1.f / Stl[sp * 2 + 1];
    float4 o0 = make_float4(acc[0][0] * inv0, acc[0][1] * inv0,
                            acc[0][2] * inv0, acc[0][3] * inv0);
    float4 o1 = make_float4(acc[1][0] * inv1, acc[1][1] * inv1,
                            acc[1][2] * inv1, acc[1][3] * inv1);
    *(float4*)(ctxg + (size_t)(slot_base + sp * 2) * HD_ + d0) = o0;
    *(float4*)(ctxg + (size_t)(slot_base + sp * 2 + 1) * HD_ + d0) = o1;
}

// ---------------------------------------------------------------------------
// Host launcher
// ---------------------------------------------------------------------------
extern "C" void kernel_launch(void* const* d_in, const int* in_sizes, int n_in,
                              void* d_out, int out_size) {
    const float* src  = (const float*)d_in[0];
    const float* ln1w = (const float*)d_in[1];
    const float* ln1b = (const float*)d_in[2];
    const float* ln2w = (const float*)d_in[3];
    const float* ln2b = (const float*)d_in[4];
    const float* agw  = (const float*)d_in[5];
    const float* qw   = (const float*)d_in[6];
    const float* qb   = (const float*)d_in[7];
    const float* kw   = (const float*)d_in[8];
    const float* kb   = (const float*)d_in[9];
    const float* vw   = (const float*)d_in[10];
    const float* vb   = (const float*)d_in[11];
    const float* ow   = (const float*)d_in[12];
    const float* ob   = (const float*)d_in[13];
    const float* rel  = (const float*)d_in[14];
    const float* fgw  = (const float*)d_in[15];
    const float* w1   = (const float*)d_in[16];
    const float* b1   = (const float*)d_in[17];
    const float* w2   = (const float*)d_in[18];
    const float* b2   = (const float*)d_in[19];
    float* out = (float*)d_out;

    float *xn, *xmid, *xn2, *kp, *vp, *qp, *ctx, *ya, *yf, *gwa, *gwf;
    int *cnta, *cntf, *lista, *listf;
    __nv_bfloat16 *xn2bf, *hbf, *w1t, *w2t;
    cudaGetSymbolAddress((void**)&xn,    g_xn);
    cudaGetSymbolAddress((void**)&xmid,  g_xmid);
    cudaGetSymbolAddress((void**)&xn2,   g_xn2);
    cudaGetSymbolAddress((void**)&kp,    g_k);
    cudaGetSymbolAddress((void**)&vp,    g_v);
    cudaGetSymbolAddress((void**)&qp,    g_q);
    cudaGetSymbolAddress((void**)&ctx,   g_ctx);
    cudaGetSymbolAddress((void**)&ya,    g_ya);
    cudaGetSymbolAddress((void**)&yf,    g_yf);
    cudaGetSymbolAddress((void**)&gwa,   g_gwa);
    cudaGetSymbolAddress((void**)&gwf,   g_gwf);
    cudaGetSymbolAddress((void**)&cnta,  g_cnt_a);
    cudaGetSymbolAddress((void**)&cntf,  g_cnt_f);
    cudaGetSymbolAddress((void**)&lista, g_list_a);
    cudaGetSymbolAddress((void**)&listf, g_list_f);
    cudaGetSymbolAddress((void**)&xn2bf, g_xn2_bf);
    cudaGetSymbolAddress((void**)&hbf,   g_h_bf);
    cudaGetSymbolAddress((void**)&w1t,   g_w1t);
    cudaGetSymbolAddress((void**)&w2t,   g_w2t);

    static bool attr_set = []() {
        cudaFuncSetAttribute(attn_k, cudaFuncAttributeMaxDynamicSharedMemorySize,
                             ATT_SMEM_BYTES);
        return true;
    }();
    (void)attr_set;

    zero_k<<<1, 32>>>();

    // bf16 transposed weight shadows (w1: [E][D][FH]->[E][FH][D], w2: [E][FH][D]->[E][D][FH])
    convT_k<D_, FH_><<<dim3(FH_ / 32, D_ / 32, EF_), 256>>>(w1, w1t);
    convT_k<FH_, D_><<<dim3(D_ / 32, FH_ / 32, EF_), 256>>>(w2, w2t);

    ln1_k<<<NTOK_, 256>>>(src, ln1w, ln1b, xn);

    // shared k/v projections fused into one launch (z picks weights)
    dim3 gkv(HD_ / 64, NTOK_ / 128, 2);
    gemm_k<0, false, false><<<gkv, 256>>>(xn, D_, kw, kb, kp, HD_,
                                          vw, vb, vp,
                                          nullptr, nullptr, nullptr,
                                          HD_, D_, NTOK_, 1.f);

    route_attn_k<<<NTOK_ / 8, 256>>>(xn, agw);

    // per-expert Q projection (gathered), scaled by HD^-0.5
    dim3 gq(HD_ / 64, CAP_ / 128, EA_);
    gemm_k<1, false, false><<<gq, 256>>>(xn, D_, qw, qb, qp, HD_,
                                         nullptr, nullptr, nullptr,
                                         lista, cnta, nullptr,
                                         HD_, D_, 0, 0.08838834764831845f);

    dim3 gat(128, B_);
    attn_k<<<gat, 256, ATT_SMEM_BYTES>>>(qp, kp, vp, rel, ctx);

    // per-expert output projection, gated (fp32)
    dim3 go(D_ / 64, CAP_ / 128, EA_);
    gemm_k<2, false, true><<<go, 256>>>(ctx, HD_, ow, ob, ya, D_,
                                        nullptr, nullptr, nullptr,
                                        lista, cnta, gwa,
                                        D_, HD_, 0, 1.f);

    combine_ln2_k<<<NTOK_, 256>>>(src, ya, ln2w, ln2b, xmid, xn2, xn2bf);
    route_ffn_k<<<NTOK_ / 8, 256>>>(xn2, fgw);

    // FFN via bf16 mma.sync tensor cores
    dim3 g1(FH_ / 128, CAP_ / 128, EF_);
    mmasync_ffn_k<D_, 1, true, false, true><<<g1, 256>>>(
        xn2bf, w1t, b1, FH_, (void*)hbf, FH_, listf, cntf, nullptr);
    dim3 g2(D_ / 128, CAP_ / 128, EF_);
    mmasync_ffn_k<FH_, 2, false, true, false><<<g2, 256>>>(
        hbf, w2t, b2, D_, (void*)yf, D_, listf, cntf, gwf);

    final_k<<<NTOK_, 256>>>(xmid, yf, out);
}

// round 6
// speedup vs baseline: 1.8229x; 1.2041x over previous
#include <cuda_runtime.h>
#include <cuda_bf16.h>
#include <math.h>
#include <stdint.h>

// ---------------------------------------------------------------------------
// Problem constants
// ---------------------------------------------------------------------------
#define D_    1024
#define HD_   128
#define EA_   8
#define EF_   16
#define FH_   512
#define S_    1024
#define B_    4
#define NTOK_ 4096           // B*S
#define NTS_  8192           // NTOK*2 slots (top-2)
#define CAP_  4096           // max rows per expert

// ---------------------------------------------------------------------------
// mma.sync helpers (baseline PTX, compiles for compute_103)
// ---------------------------------------------------------------------------
__device__ __forceinline__ uint32_t smem_to_u32(const void* p) {
    uint32_t a;
    asm("{ .reg .u64 t; cvta.to.shared.u64 t, %1; cvt.u32.u64 %0, t; }"
        : "=r"(a) : "l"(p));
    return a;
}
__device__ __forceinline__ void ldsm4(uint32_t& r0, uint32_t& r1,
                                      uint32_t& r2, uint32_t& r3, uint32_t a) {
    asm volatile("ldmatrix.sync.aligned.m8n8.x4.shared.b16 {%0,%1,%2,%3}, [%4];"
                 : "=r"(r0), "=r"(r1), "=r"(r2), "=r"(r3) : "r"(a));
}
__device__ __forceinline__ void mma16816(float* c, const uint32_t* a,
                                         const uint32_t* b) {
    asm volatile(
        "mma.sync.aligned.m16n8k16.row.col.f32.bf16.bf16.f32 "
        "{%0,%1,%2,%3}, {%4,%5,%6,%7}, {%8,%9}, {%0,%1,%2,%3};"
        : "+f"(c[0]), "+f"(c[1]), "+f"(c[2]), "+f"(c[3])
        : "r"(a[0]), "r"(a[1]), "r"(a[2]), "r"(a[3]), "r"(b[0]), "r"(b[1]));
}

// ---------------------------------------------------------------------------
// Device-global scratch (allocation-free)
// ---------------------------------------------------------------------------
__device__ float g_xn  [NTOK_ * D_];
__device__ float g_xmid[NTOK_ * D_];
__device__ float g_xn2 [NTOK_ * D_];
__device__ float g_kv  [2 * NTOK_ * HD_];   // [0]=K, [1]=V
__device__ float g_q   [NTS_  * HD_];
__device__ float g_ya  [NTS_  * D_];
__device__ float g_yf  [NTS_  * D_];
__device__ float g_gwa [NTS_];
__device__ float g_gwf [NTS_];
__device__ int   g_cnt_a [EA_];
__device__ int   g_cnt_f [EF_];
__device__ int   g_cnt_id[2];
__device__ int   g_list_a[EA_ * CAP_];
__device__ int   g_list_f[EF_ * CAP_];
__device__ int   g_list_id[2 * CAP_];
__device__ float g_kvb [2 * HD_];           // packed k_b, v_b
// bf16 shadows for tensor-core GEMMs
__device__ __nv_bfloat16 g_xn_bf [NTOK_ * D_];
__device__ __nv_bfloat16 g_xn2_bf[NTOK_ * D_];
__device__ __nv_bfloat16 g_ctx_bf[NTS_  * HD_];
__device__ __nv_bfloat16 g_h_bf  [NTS_  * FH_];
__device__ __nv_bfloat16 g_w1t   [EF_ * FH_ * D_];   // [e][n=FH][k=D]
__device__ __nv_bfloat16 g_w2t   [EF_ * D_ * FH_];   // [e][n=D][k=FH]
__device__ __nv_bfloat16 g_qwt   [EA_ * HD_ * D_];   // [e][n=HD][k=D]
__device__ __nv_bfloat16 g_owt   [EA_ * D_ * HD_];   // [e][n=D][k=HD]
__device__ __nv_bfloat16 g_kvwt  [2 * HD_ * D_];     // [kv][n=HD][k=D]

// ---------------------------------------------------------------------------
// Setup: zero counters, identity list, packed kv bias
// ---------------------------------------------------------------------------
__global__ void __launch_bounds__(256) setup_k(const float* __restrict__ kb,
                                               const float* __restrict__ vb) {
    int i = blockIdx.x * 256 + threadIdx.x;
    if (i < EA_) g_cnt_a[i] = 0;
    if (i < EF_) g_cnt_f[i] = 0;
    if (i < 2)   g_cnt_id[i] = NTOK_;
    if (i < 2 * CAP_) g_list_id[i] = i & (CAP_ - 1);
    if (i < HD_) g_kvb[i] = kb[i];
    else if (i < 2 * HD_) g_kvb[i] = vb[i - HD_];
}

// ---------------------------------------------------------------------------
// Weight transpose + fp32->bf16 convert: W[E][K][N] -> O[E][N][K]
// ---------------------------------------------------------------------------
template<int K, int N>
__global__ void __launch_bounds__(256) convT_k(const float* __restrict__ W,
                                               __nv_bfloat16* __restrict__ O) {
    __shared__ float t[32][33];
    int e = blockIdx.z;
    int k0 = blockIdx.y * 32, n0 = blockIdx.x * 32;
    const float* w = W + (size_t)e * K * N;
    __nv_bfloat16* o = O + (size_t)e * N * K;
    int tx = threadIdx.x & 31, ty = threadIdx.x >> 5;
    #pragma unroll
    for (int i = 0; i < 32; i += 8)
        t[ty + i][tx] = w[(size_t)(k0 + ty + i) * N + n0 + tx];
    __syncthreads();
    #pragma unroll
    for (int i = 0; i < 32; i += 8)
        o[(size_t)(n0 + ty + i) * K + k0 + tx] = __float2bfloat16(t[tx][ty + i]);
}

// ---------------------------------------------------------------------------
// LayerNorm 1 (fp32 out + bf16 shadow)
// ---------------------------------------------------------------------------
__global__ void __launch_bounds__(256) ln1_k(
    const float* __restrict__ x, const float* __restrict__ w,
    const float* __restrict__ b, float* __restrict__ y,
    __nv_bfloat16* __restrict__ ybf)
{
    int t = blockIdx.x, tid = threadIdx.x;
    float4 v = ((const float4*)(x + (size_t)t * D_))[tid];
    float s = v.x + v.y + v.z + v.w;
    float q = fmaf(v.x, v.x, fmaf(v.y, v.y, fmaf(v.z, v.z, v.w * v.w)));
    __shared__ float ss[8], sq[8];
    #pragma unroll
    for (int o = 16; o; o >>= 1) {
        s += __shfl_xor_sync(0xffffffffu, s, o);
        q += __shfl_xor_sync(0xffffffffu, q, o);
    }
    if ((tid & 31) == 0) { ss[tid >> 5] = s; sq[tid >> 5] = q; }
    __syncthreads();
    if (tid == 0) {
        float a = 0.f, c = 0.f;
        #pragma unroll
        for (int i = 0; i < 8; i++) { a += ss[i]; c += sq[i]; }
        ss[0] = a; sq[0] = c;
    }
    __syncthreads();
    float mu  = ss[0] * (1.f / D_);
    float var = sq[0] * (1.f / D_) - mu * mu;
    float rs  = rsqrtf(var + 1e-5f);
    float4 wv = ((const float4*)w)[tid];
    float4 bv = ((const float4*)b)[tid];
    float4 o;
    o.x = (v.x - mu) * rs * wv.x + bv.x;
    o.y = (v.y - mu) * rs * wv.y + bv.y;
    o.z = (v.z - mu) * rs * wv.z + bv.z;
    o.w = (v.w - mu) * rs * wv.w + bv.w;
    ((float4*)(y + (size_t)t * D_))[tid] = o;
    __nv_bfloat162 p0 = __floats2bfloat162_rn(o.x, o.y);
    __nv_bfloat162 p1 = __floats2bfloat162_rn(o.z, o.w);
    uint2 st;
    st.x = *(uint32_t*)&p0; st.y = *(uint32_t*)&p1;
    *(uint2*)(ybf + (size_t)t * D_ + tid * 4) = st;
}

// Residual-add of two slot rows + LayerNorm fused (writes xmid, xn2 fp32 + bf16)
__global__ void __launch_bounds__(256) combine_ln2_k(
    const float* __restrict__ src, const float* __restrict__ ya,
    const float* __restrict__ w, const float* __restrict__ b,
    float* __restrict__ xmid, float* __restrict__ xn2,
    __nv_bfloat16* __restrict__ xn2bf)
{
    int t = blockIdx.x, tid = threadIdx.x;
    float4 v  = ((const float4*)(src + (size_t)t * D_))[tid];
    float4 y0 = ((const float4*)(ya + (size_t)(2 * t) * D_))[tid];
    float4 y1 = ((const float4*)(ya + (size_t)(2 * t + 1) * D_))[tid];
    v.x += y0.x + y1.x; v.y += y0.y + y1.y;
    v.z += y0.z + y1.z; v.w += y0.w + y1.w;
    ((float4*)(xmid + (size_t)t * D_))[tid] = v;

    float s = v.x + v.y + v.z + v.w;
    float q = fmaf(v.x, v.x, fmaf(v.y, v.y, fmaf(v.z, v.z, v.w * v.w)));
    __shared__ float ss[8], sq[8];
    #pragma unroll
    for (int o = 16; o; o >>= 1) {
        s += __shfl_xor_sync(0xffffffffu, s, o);
        q += __shfl_xor_sync(0xffffffffu, q, o);
    }
    if ((tid & 31) == 0) { ss[tid >> 5] = s; sq[tid >> 5] = q; }
    __syncthreads();
    if (tid == 0) {
        float a = 0.f, c = 0.f;
        #pragma unroll
        for (int i = 0; i < 8; i++) { a += ss[i]; c += sq[i]; }
        ss[0] = a; sq[0] = c;
    }
    __syncthreads();
    float mu  = ss[0] * (1.f / D_);
    float var = sq[0] * (1.f / D_) - mu * mu;
    float rs  = rsqrtf(var + 1e-5f);
    float4 wv = ((const float4*)w)[tid];
    float4 bv = ((const float4*)b)[tid];
    float4 o;
    o.x = (v.x - mu) * rs * wv.x + bv.x;
    o.y = (v.y - mu) * rs * wv.y + bv.y;
    o.z = (v.z - mu) * rs * wv.z + bv.z;
    o.w = (v.w - mu) * rs * wv.w + bv.w;
    ((float4*)(xn2 + (size_t)t * D_))[tid] = o;
    __nv_bfloat162 p0 = __floats2bfloat162_rn(o.x, o.y);
    __nv_bfloat162 p1 = __floats2bfloat162_rn(o.z, o.w);
    uint2 st;
    st.x = *(uint32_t*)&p0; st.y = *(uint32_t*)&p1;
    *(uint2*)(xn2bf + (size_t)t * D_ + tid * 4) = st;
}

// out = xmid + yf[2t] + yf[2t+1]
__global__ void __launch_bounds__(256) final_k(
    const float* __restrict__ xmid, const float* __restrict__ yf,
    float* __restrict__ out)
{
    int t = blockIdx.x, tid = threadIdx.x;
    float4 v  = ((const float4*)(xmid + (size_t)t * D_))[tid];
    float4 y0 = ((const float4*)(yf + (size_t)(2 * t) * D_))[tid];
    float4 y1 = ((const float4*)(yf + (size_t)(2 * t + 1) * D_))[tid];
    v.x += y0.x + y1.x; v.y += y0.y + y1.y;
    v.z += y0.z + y1.z; v.w += y0.w + y1.w;
    ((float4*)(out + (size_t)t * D_))[tid] = v;
}

// ---------------------------------------------------------------------------
// Routers (one warp per token, top-2, atomic list append)
// ---------------------------------------------------------------------------
__global__ void __launch_bounds__(256) route_attn_k(
    const float* __restrict__ xn, const float* __restrict__ gwm)
{
    int t = blockIdx.x * 8 + (threadIdx.x >> 5);
    int lane = threadIdx.x & 31;
    const float* x = xn + (size_t)t * D_;
    float acc[EA_];
    #pragma unroll
    for (int e = 0; e < EA_; e++) acc[e] = 0.f;
    for (int d = lane; d < D_; d += 32) {
        float xv = x[d];
        const float4* g4 = (const float4*)(gwm + (size_t)d * EA_);
        float4 ga = g4[0], gb = g4[1];
        acc[0] = fmaf(xv, ga.x, acc[0]); acc[1] = fmaf(xv, ga.y, acc[1]);
        acc[2] = fmaf(xv, ga.z, acc[2]); acc[3] = fmaf(xv, ga.w, acc[3]);
        acc[4] = fmaf(xv, gb.x, acc[4]); acc[5] = fmaf(xv, gb.y, acc[5]);
        acc[6] = fmaf(xv, gb.z, acc[6]); acc[7] = fmaf(xv, gb.w, acc[7]);
    }
    #pragma unroll
    for (int e = 0; e < EA_; e++)
        #pragma unroll
        for (int o = 16; o; o >>= 1)
            acc[e] += __shfl_xor_sync(0xffffffffu, acc[e], o);
    if (lane == 0) {
        int i0 = 0; float v0 = acc[0];
        #pragma unroll
        for (int e = 1; e < EA_; e++) if (acc[e] > v0) { v0 = acc[e]; i0 = e; }
        int i1 = -1; float v1 = -1e30f;
        #pragma unroll
        for (int e = 0; e < EA_; e++)
            if (e != i0 && acc[e] > v1) { v1 = acc[e]; i1 = e; }
        float e1 = __expf(v1 - v0);
        float inv = 1.f / (1.f + e1);
        g_gwa[2 * t]     = inv;
        g_gwa[2 * t + 1] = e1 * inv;
        int p0 = atomicAdd(&g_cnt_a[i0], 1);
        g_list_a[i0 * CAP_ + p0] = 2 * t;
        int p1 = atomicAdd(&g_cnt_a[i1], 1);
        g_list_a[i1 * CAP_ + p1] = 2 * t + 1;
    }
}

__global__ void __launch_bounds__(256) route_ffn_k(
    const float* __restrict__ xn, const float* __restrict__ gwm)
{
    int t = blockIdx.x * 8 + (threadIdx.x >> 5);
    int lane = threadIdx.x & 31;
    const float* x = xn + (size_t)t * D_;
    float acc[EF_];
    #pragma unroll
    for (int e = 0; e < EF_; e++) acc[e] = 0.f;
    for (int d = lane; d < D_; d += 32) {
        float xv = x[d];
        const float4* g4 = (const float4*)(gwm + (size_t)d * EF_);
        #pragma unroll
        for (int g = 0; g < 4; g++) {
            float4 gv = g4[g];
            acc[g*4+0] = fmaf(xv, gv.x, acc[g*4+0]);
            acc[g*4+1] = fmaf(xv, gv.y, acc[g*4+1]);
            acc[g*4+2] = fmaf(xv, gv.z, acc[g*4+2]);
            acc[g*4+3] = fmaf(xv, gv.w, acc[g*4+3]);
        }
    }
    #pragma unroll
    for (int e = 0; e < EF_; e++)
        #pragma unroll
        for (int o = 16; o; o >>= 1)
            acc[e] += __shfl_xor_sync(0xffffffffu, acc[e], o);
    if (lane == 0) {
        int i0 = 0; float v0 = acc[0];
        #pragma unroll
        for (int e = 1; e < EF_; e++) if (acc[e] > v0) { v0 = acc[e]; i0 = e; }
        int i1 = -1; float v1 = -1e30f;
        #pragma unroll
        for (int e = 0; e < EF_; e++)
            if (e != i0 && acc[e] > v1) { v1 = acc[e]; i1 = e; }
        float e1 = __expf(v1 - v0);
        float inv = 1.f / (1.f + e1);
        g_gwf[2 * t]     = inv;
        g_gwf[2 * t + 1] = e1 * inv;
        int p0 = atomicAdd(&g_cnt_f[i0], 1);
        g_list_f[i0 * CAP_ + p0] = 2 * t;
        int p1 = atomicAdd(&g_cnt_f[i1], 1);
        g_list_f[i1 * CAP_ + p1] = 2 * t + 1;
    }
}

// ---------------------------------------------------------------------------
// bf16 mma.sync grouped/gather GEMM (all projections + FFN).
// BM=128, BN=128, BK=64. 8 warps in 4(M)x2(N); warp tile 32x64 = 2x8 HMMA.16816.
// A row = TOKROW ? list[r]>>1 : list[r]. Y += e*eStrideY + slot*ldy.
// Epilogue: y = relu?((acc+bias)*scale) * gate
// ---------------------------------------------------------------------------
#define LDAB 72   // bf16 elements per smem row (64 + 8 pad): 144B stride

template<int KTOT, bool TOKROW, bool RELU, bool GATE, bool OUTBF>
__global__ void __launch_bounds__(256) mmasync_gemm_k(
    const __nv_bfloat16* __restrict__ Abase,
    const __nv_bfloat16* __restrict__ Bbase,
    const float* __restrict__ biasb, int Nfull,
    void* __restrict__ Yv, int ldy, size_t eStrideY,
    const int* __restrict__ lists, const int* __restrict__ cnts,
    const float* __restrict__ gw, float scale)
{
    int e = blockIdx.z;
    int cnt = cnts[e];
    int row0 = blockIdx.y * 128;
    if (row0 >= cnt) return;
    int n0 = blockIdx.x * 128;
    const int* list = lists + e * CAP_;

    __shared__ __nv_bfloat16 As[128 * LDAB];
    __shared__ __nv_bfloat16 Bs[128 * LDAB];
    __shared__ float bias_s[128];
    __shared__ float gate_s[128];
    __shared__ int   slot_s[128];

    int tid = threadIdx.x;
    int wid = tid >> 5, lane = tid & 31;

    if (tid < 128) {
        int r = min(row0 + tid, cnt - 1);
        int sl = list[r];
        slot_s[tid] = sl;
        gate_s[tid] = GATE ? gw[sl] : 1.f;
        bias_s[tid] = biasb[(size_t)e * Nfull + n0 + tid];
    }

    const __nv_bfloat16* Bexp = Bbase + (size_t)e * Nfull * KTOT;
    const __nv_bfloat16* aSrc[4];
    const __nv_bfloat16* bSrc[4];
    uint32_t aDst[4], bDst[4];
    uint32_t sA = smem_to_u32(As), sB = smem_to_u32(Bs);
    #pragma unroll
    for (int i = 0; i < 4; i++) {
        int idx = tid + i * 256;
        int m = idx >> 3, c = idx & 7;
        int r = min(row0 + m, cnt - 1);
        int sl = list[r];
        int gr = TOKROW ? (sl >> 1) : sl;
        aSrc[i] = Abase + (size_t)gr * KTOT + c * 8;
        bSrc[i] = Bexp + (size_t)(n0 + m) * KTOT + c * 8;
        aDst[i] = sA + (m * LDAB + c * 8) * 2;
        bDst[i] = sB + (m * LDAB + c * 8) * 2;
    }

    int warpM = (wid & 3) * 32;
    int warpN = (wid >> 2) * 64;
    uint32_t aAddr = sA + ((warpM + (lane & 15)) * LDAB + (lane >> 4) * 8) * 2;
    uint32_t bAddr = sB + ((warpN + ((lane >> 4) & 1) * 8 + (lane & 7)) * LDAB
                           + ((lane >> 3) & 1) * 8) * 2;

    float acc[2][8][4];
    #pragma unroll
    for (int mt = 0; mt < 2; mt++)
        #pragma unroll
        for (int nt = 0; nt < 8; nt++)
            #pragma unroll
            for (int j = 0; j < 4; j++) acc[mt][nt][j] = 0.f;

    uint4 aR[4], bR[4];
    #pragma unroll
    for (int i = 0; i < 4; i++) {
        aR[i] = *(const uint4*)(aSrc[i]);
        bR[i] = *(const uint4*)(bSrc[i]);
    }

    const int NSTAGE = KTOT / 64;
    for (int st = 0; st < NSTAGE; st++) {
        __syncthreads();
        #pragma unroll
        for (int i = 0; i < 4; i++) {
            asm volatile("st.shared.v4.b32 [%0], {%1,%2,%3,%4};" ::
                "r"(aDst[i]), "r"(aR[i].x), "r"(aR[i].y), "r"(aR[i].z), "r"(aR[i].w));
            asm volatile("st.shared.v4.b32 [%0], {%1,%2,%3,%4};" ::
                "r"(bDst[i]), "r"(bR[i].x), "r"(bR[i].y), "r"(bR[i].z), "r"(bR[i].w));
        }
        __syncthreads();
        if (st + 1 < NSTAGE) {
            int k0 = (st + 1) * 64;
            #pragma unroll
            for (int i = 0; i < 4; i++) {
                aR[i] = *(const uint4*)(aSrc[i] + k0);
                bR[i] = *(const uint4*)(bSrc[i] + k0);
            }
        }
        #pragma unroll
        for (int kk = 0; kk < 4; kk++) {
            uint32_t a[2][4];
            ldsm4(a[0][0], a[0][1], a[0][2], a[0][3], aAddr + kk * 32);
            ldsm4(a[1][0], a[1][1], a[1][2], a[1][3],
                  aAddr + 16 * LDAB * 2 + kk * 32);
            uint32_t b[8][2];
            #pragma unroll
            for (int nt2 = 0; nt2 < 4; nt2++) {
                uint32_t r0, r1, r2, r3;
                ldsm4(r0, r1, r2, r3, bAddr + nt2 * 16 * LDAB * 2 + kk * 32);
                b[nt2 * 2][0] = r0;     b[nt2 * 2][1] = r1;
                b[nt2 * 2 + 1][0] = r2; b[nt2 * 2 + 1][1] = r3;
            }
            #pragma unroll
            for (int mt = 0; mt < 2; mt++)
                #pragma unroll
                for (int nt = 0; nt < 8; nt++)
                    mma16816(acc[mt][nt], a[mt], b[nt]);
        }
    }

    // Epilogue
    int lane4 = lane >> 2;
    int lcol  = (lane & 3) * 2;
    #pragma unroll
    for (int mt = 0; mt < 2; mt++) {
        #pragma unroll
        for (int h = 0; h < 2; h++) {
            int m = warpM + mt * 16 + lane4 + h * 8;
            if (row0 + m >= cnt) continue;
            int sl = slot_s[m];
            float f = gate_s[m];
            size_t ybase = (size_t)e * eStrideY + (size_t)sl * ldy + n0;
            #pragma unroll
            for (int nt = 0; nt < 8; nt++) {
                int col = warpN + nt * 8 + lcol;
                float v0 = (acc[mt][nt][h * 2 + 0] + bias_s[col]) * scale;
                float v1 = (acc[mt][nt][h * 2 + 1] + bias_s[col + 1]) * scale;
                if (RELU) { v0 = fmaxf(v0, 0.f); v1 = fmaxf(v1, 0.f); }
                v0 *= f; v1 *= f;
                if (OUTBF) {
                    __nv_bfloat162 p = __floats2bfloat162_rn(v0, v1);
                    *(uint32_t*)((__nv_bfloat16*)Yv + ybase + col) = *(uint32_t*)&p;
                } else {
                    float2 p = make_float2(v0, v1);
                    *(float2*)((float*)Yv + ybase + col) = p;
                }
            }
        }
    }
}

// ---------------------------------------------------------------------------
// Attention (fp32; ctx emitted as bf16 for the o-projection)
// ---------------------------------------------------------------------------
#define ATT_SMEM_FLOATS (2112 + 2112 + 1088 + 64 + 17152)
#define ATT_SMEM_BYTES  (ATT_SMEM_FLOATS * 4)

__global__ void __launch_bounds__(256) attn_k(
    const float* __restrict__ qg, const float* __restrict__ kg,
    const float* __restrict__ vg, const float* __restrict__ rel,
    __nv_bfloat16* __restrict__ ctxbf)
{
    extern __shared__ float smf[];
    float* Qs  = smf;
    float* Rl  = smf + 2112;
    float* Sb  = smf + 4224;
    float* Stm = smf + 5312;
    float* Stl = Stm + 16;
    float* Stc = Stm + 32;
    float* Big = smf + 5376;
    float* Kt   = Big;
    float* Vs   = Big + 8704;
    float* RelT = Big;

    int b = blockIdx.y;
    int qt = blockIdx.x;
    int slot_base = b * 2048 + qt * 16;
    int tid = threadIdx.x;

    for (int i = tid; i < 512; i += 256) {
        int r = i >> 5, c = i & 31;
        float4 v = ((const float4*)(qg + (size_t)(slot_base + r) * HD_))[c];
        float* q = Qs + r * 132 + c * 4;
        q[0] = v.x; q[1] = v.y; q[2] = v.z; q[3] = v.w;
    }
    for (int i = tid; i < 129 * 32; i += 256) {
        int r = i >> 5, c = i & 31;
        float4 v = ((const float4*)(rel + (size_t)r * HD_))[c];
        RelT[(c * 4 + 0) * 132 + r] = v.x;
        RelT[(c * 4 + 1) * 132 + r] = v.y;
        RelT[(c * 4 + 2) * 132 + r] = v.z;
        RelT[(c * 4 + 3) * 132 + r] = v.w;
    }
    if (tid < 16) { Stm[tid] = -1e30f; Stl[tid] = 0.f; }
    __syncthreads();

    for (int task = tid; task < 16 * 33; task += 256) {
        int slot = task / 33, rg = task % 33;
        const float* qrow = Qs + slot * 132;
        float a0 = 0, a1 = 0, a2 = 0, a3 = 0;
        #pragma unroll 8
        for (int kk = 0; kk < 128; kk++) {
            float qv = qrow[kk];
            float4 rv = *(const float4*)&RelT[kk * 132 + rg * 4];
            a0 = fmaf(qv, rv.x, a0); a1 = fmaf(qv, rv.y, a1);
            a2 = fmaf(qv, rv.z, a2); a3 = fmaf(qv, rv.w, a3);
        }
        float* o = Rl + slot * 132 + rg * 4;
        o[0] = a0; o[1] = a1; o[2] = a2; o[3] = a3;
    }

    int sc_slot = tid >> 4;
    int sc_jg   = tid & 15;
    int s_q = (qt * 16 + sc_slot) >> 1;
    int sp  = tid >> 5;
    int d0  = (tid & 31) * 4;
    float acc[2][4] = {{0, 0, 0, 0}, {0, 0, 0, 0}};

    for (int kt = 0; kt < 16; kt++) {
        int j0 = kt * 64;
        __syncthreads();
        for (int i = tid; i < 64 * 32; i += 256) {
            int j = i >> 5, c = i & 31;
            float4 kv = ((const float4*)(kg + (size_t)(b * S_ + j0 + j) * HD_))[c];
            Kt[(c * 4 + 0) * 68 + j] = kv.x;
            Kt[(c * 4 + 1) * 68 + j] = kv.y;
            Kt[(c * 4 + 2) * 68 + j] = kv.z;
            Kt[(c * 4 + 3) * 68 + j] = kv.w;
            float4 vv = ((const float4*)(vg + (size_t)(b * S_ + j0 + j) * HD_))[c];
            *(float4*)&Vs[j * 132 + c * 4] = vv;
        }
        __syncthreads();
        float s[4] = {0, 0, 0, 0};
        {
            const float* qrow = Qs + sc_slot * 132;
            #pragma unroll 8
            for (int kk = 0; kk < 128; kk++) {
                float qv = qrow[kk];
                float4 kv = *(const float4*)&Kt[kk * 68 + sc_jg * 4];
                s[0] = fmaf(qv, kv.x, s[0]); s[1] = fmaf(qv, kv.y, s[1]);
                s[2] = fmaf(qv, kv.z, s[2]); s[3] = fmaf(qv, kv.w, s[3]);
            }
        }
        #pragma unroll
        for (int u = 0; u < 4; u++) {
            int j = j0 + sc_jg * 4 + u;
            int rr = j - s_q;
            rr = max(-64, min(64, rr)) + 64;
            s[u] += Rl[sc_slot * 132 + rr];
        }
        float mx = fmaxf(fmaxf(s[0], s[1]), fmaxf(s[2], s[3]));
        #pragma unroll
        for (int o = 8; o; o >>= 1)
            mx = fmaxf(mx, __shfl_xor_sync(0xffffffffu, mx, o));
        float m_old = Stm[sc_slot];
        float m_new = fmaxf(m_old, mx);
        float ps = 0.f;
        #pragma unroll
        for (int u = 0; u < 4; u++) { s[u] = __expf(s[u] - m_new); ps += s[u]; }
        #pragma unroll
        for (int o = 8; o; o >>= 1)
            ps += __shfl_xor_sync(0xffffffffu, ps, o);
        *(float4*)&Sb[sc_slot * 68 + sc_jg * 4] = make_float4(s[0], s[1], s[2], s[3]);
        if ((tid & 15) == 0) {
            float scl = __expf(m_old - m_new);
            Stc[sc_slot] = scl;
            Stl[sc_slot] = Stl[sc_slot] * scl + ps;
            Stm[sc_slot] = m_new;
        }
        __syncthreads();
        float sc0 = Stc[sp * 2], sc1 = Stc[sp * 2 + 1];
        #pragma unroll
        for (int u = 0; u < 4; u++) { acc[0][u] *= sc0; acc[1][u] *= sc1; }
        const float* p0r = Sb + (sp * 2) * 68;
        const float* p1r = Sb + (sp * 2 + 1) * 68;
        #pragma unroll 4
        for (int j = 0; j < 64; j++) {
            float p0 = p0r[j], p1 = p1r[j];
            float4 vv = *(const float4*)&Vs[j * 132 + d0];
            acc[0][0] = fmaf(p0, vv.x, acc[0][0]); acc[0][1] = fmaf(p0, vv.y, acc[0][1]);
            acc[0][2] = fmaf(p0, vv.z, acc[0][2]); acc[0][3] = fmaf(p0, vv.w, acc[0][3]);
            acc[1][0] = fmaf(p1, vv.x, acc[1][0]); acc[1][1] = fmaf(p1, vv.y, acc[1][1]);
            acc[1][2] = fmaf(p1, vv.z, acc[1][2]); acc[1][3] = fmaf(p1, vv.w, acc[1][3]);
        }
    }
    float inv0 = 1.f / Stl[sp * 2];
    float inv1 = 1.f / Stl[sp * 2 + 1];
    {
        __nv_bfloat162 c0 = __floats2bfloat162_rn(acc[0][0] * inv0, acc[0][1] * inv0);
        __nv_bfloat162 c1 = __floats2bfloat162_rn(acc[0][2] * inv0, acc[0][3] * inv0);
        uint2 st; st.x = *(uint32_t*)&c0; st.y = *(uint32_t*)&c1;
        *(uint2*)(ctxbf + (size_t)(slot_base + sp * 2) * HD_ + d0) = st;
        __nv_bfloat162 c2 = __floats2bfloat162_rn(acc[1][0] * inv1, acc[1][1] * inv1);
        __nv_bfloat162 c3 = __floats2bfloat162_rn(acc[1][2] * inv1, acc[1][3] * inv1);
        uint2 st2; st2.x = *(uint32_t*)&c2; st2.y = *(uint32_t*)&c3;
        *(uint2*)(ctxbf + (size_t)(slot_base + sp * 2 + 1) * HD_ + d0) = st2;
    }
}

// ---------------------------------------------------------------------------
// Host launcher
// ---------------------------------------------------------------------------
extern "C" void kernel_launch(void* const* d_in, const int* in_sizes, int n_in,
                              void* d_out, int out_size) {
    const float* src  = (const float*)d_in[0];
    const float* ln1w = (const float*)d_in[1];
    const float* ln1b = (const float*)d_in[2];
    const float* ln2w = (const float*)d_in[3];
    const float* ln2b = (const float*)d_in[4];
    const float* agw  = (const float*)d_in[5];
    const float* qw   = (const float*)d_in[6];
    const float* qb   = (const float*)d_in[7];
    const float* kw   = (const float*)d_in[8];
    const float* kb   = (const float*)d_in[9];
    const float* vw   = (const float*)d_in[10];
    const float* vb   = (const float*)d_in[11];
    const float* ow   = (const float*)d_in[12];
    const float* ob   = (const float*)d_in[13];
    const float* rel  = (const float*)d_in[14];
    const float* fgw  = (const float*)d_in[15];
    const float* w1   = (const float*)d_in[16];
    const float* b1   = (const float*)d_in[17];
    const float* w2   = (const float*)d_in[18];
    const float* b2   = (const float*)d_in[19];
    float* out = (float*)d_out;

    float *xn, *xmid, *xn2, *kv, *qp, *ya, *yf, *gwa, *gwf, *kvb;
    int *cnta, *cntf, *cntid, *lista, *listf, *listid;
    __nv_bfloat16 *xnbf, *xn2bf, *ctxbf, *hbf, *w1t, *w2t, *qwt, *owt, *kvwt;
    cudaGetSymbolAddress((void**)&xn,    g_xn);
    cudaGetSymbolAddress((void**)&xmid,  g_xmid);
    cudaGetSymbolAddress((void**)&xn2,   g_xn2);
    cudaGetSymbolAddress((void**)&kv,    g_kv);
    cudaGetSymbolAddress((void**)&qp,    g_q);
    cudaGetSymbolAddress((void**)&ya,    g_ya);
    cudaGetSymbolAddress((void**)&yf,    g_yf);
    cudaGetSymbolAddress((void**)&gwa,   g_gwa);
    cudaGetSymbolAddress((void**)&gwf,   g_gwf);
    cudaGetSymbolAddress((void**)&kvb,   g_kvb);
    cudaGetSymbolAddress((void**)&cnta,  g_cnt_a);
    cudaGetSymbolAddress((void**)&cntf,  g_cnt_f);
    cudaGetSymbolAddress((void**)&cntid, g_cnt_id);
    cudaGetSymbolAddress((void**)&lista, g_list_a);
    cudaGetSymbolAddress((void**)&listf, g_list_f);
    cudaGetSymbolAddress((void**)&listid,g_list_id);
    cudaGetSymbolAddress((void**)&xnbf,  g_xn_bf);
    cudaGetSymbolAddress((void**)&xn2bf, g_xn2_bf);
    cudaGetSymbolAddress((void**)&ctxbf, g_ctx_bf);
    cudaGetSymbolAddress((void**)&hbf,   g_h_bf);
    cudaGetSymbolAddress((void**)&w1t,   g_w1t);
    cudaGetSymbolAddress((void**)&w2t,   g_w2t);
    cudaGetSymbolAddress((void**)&qwt,   g_qwt);
    cudaGetSymbolAddress((void**)&owt,   g_owt);
    cudaGetSymbolAddress((void**)&kvwt,  g_kvwt);

    static bool attr_set = []() {
        cudaFuncSetAttribute(attn_k, cudaFuncAttributeMaxDynamicSharedMemorySize,
                             ATT_SMEM_BYTES);
        return true;
    }();
    (void)attr_set;

    float* kp = kv;
    float* vp = kv + (size_t)NTOK_ * HD_;

    setup_k<<<(2 * CAP_) / 256, 256>>>(kb, vb);

    // bf16 transposed weight shadows
    convT_k<D_, FH_><<<dim3(FH_ / 32, D_ / 32, EF_), 256>>>(w1, w1t);
    convT_k<FH_, D_><<<dim3(D_ / 32, FH_ / 32, EF_), 256>>>(w2, w2t);
    convT_k<D_, HD_><<<dim3(HD_ / 32, D_ / 32, EA_), 256>>>(qw, qwt);
    convT_k<HD_, D_><<<dim3(D_ / 32, HD_ / 32, EA_), 256>>>(ow, owt);
    convT_k<D_, HD_><<<dim3(HD_ / 32, D_ / 32, 1), 256>>>(kw, kvwt);
    convT_k<D_, HD_><<<dim3(HD_ / 32, D_ / 32, 1), 256>>>(vw, kvwt + (size_t)HD_ * D_);

    ln1_k<<<NTOK_, 256>>>(src, ln1w, ln1b, xn, xnbf);

    // fused K/V projection: "experts" 0/1 over identity list
    mmasync_gemm_k<D_, false, false, false, false>
        <<<dim3(1, NTOK_ / 128, 2), 256>>>(
        xnbf, kvwt, kvb, HD_, (void*)kv, HD_, (size_t)NTOK_ * HD_,
        listid, cntid, nullptr, 1.f);

    route_attn_k<<<NTOK_ / 8, 256>>>(xn, agw);

    // per-expert Q projection (gathered, scaled by HD^-0.5, fp32 out)
    mmasync_gemm_k<D_, true, false, false, false>
        <<<dim3(1, CAP_ / 128, EA_), 256>>>(
        xnbf, qwt, qb, HD_, (void*)qp, HD_, 0,
        lista, cnta, nullptr, 0.08838834764831845f);

    dim3 gat(128, B_);
    attn_k<<<gat, 256, ATT_SMEM_BYTES>>>(qp, kp, vp, rel, ctxbf);

    // per-expert output projection, gated (K=128, fp32 out)
    mmasync_gemm_k<HD_, false, false, true, false>
        <<<dim3(D_ / 128, CAP_ / 128, EA_), 256>>>(
        ctxbf, owt, ob, D_, (void*)ya, D_, 0,
        lista, cnta, gwa, 1.f);

    combine_ln2_k<<<NTOK_, 256>>>(src, ya, ln2w, ln2b, xmid, xn2, xn2bf);
    route_ffn_k<<<NTOK_ / 8, 256>>>(xn2, fgw);

    // FFN via bf16 mma.sync
    mmasync_gemm_k<D_, true, true, false, true>
        <<<dim3(FH_ / 128, CAP_ / 128, EF_), 256>>>(
        xn2bf, w1t, b1, FH_, (void*)hbf, FH_, 0,
        listf, cntf, nullptr, 1.f);
    mmasync_gemm_k<FH_, false, false, true, false>
        <<<dim3(D_ / 128, CAP_ / 128, EF_), 256>>>(
        hbf, w2t, b2, D_, (void*)yf, D_, 0,
        listf, cntf, gwf, 1.f);

    final_k<<<NTOK_, 256>>>(xmid, yf, out);
}

// round 7
// speedup vs baseline: 3.9499x; 2.1669x over previous
#include <cuda_runtime.h>
#include <cuda_bf16.h>
#include <math.h>
#include <stdint.h>

// ---------------------------------------------------------------------------
// Problem constants
// ---------------------------------------------------------------------------
#define D_    1024
#define HD_   128
#define EA_   8
#define EF_   16
#define FH_   512
#define S_    1024
#define B_    4
#define NTOK_ 4096           // B*S
#define NTS_  8192           // NTOK*2 slots (top-2)
#define CAP_  4096           // max rows per expert

// ---------------------------------------------------------------------------
// mma.sync helpers (baseline PTX, compiles for compute_103)
// ---------------------------------------------------------------------------
__device__ __forceinline__ uint32_t smem_to_u32(const void* p) {
    uint32_t a;
    asm("{ .reg .u64 t; cvta.to.shared.u64 t, %1; cvt.u32.u64 %0, t; }"
        : "=r"(a) : "l"(p));
    return a;
}
__device__ __forceinline__ void ldsm4(uint32_t& r0, uint32_t& r1,
                                      uint32_t& r2, uint32_t& r3, uint32_t a) {
    asm volatile("ldmatrix.sync.aligned.m8n8.x4.shared.b16 {%0,%1,%2,%3}, [%4];"
                 : "=r"(r0), "=r"(r1), "=r"(r2), "=r"(r3) : "r"(a));
}
__device__ __forceinline__ void ldsm4t(uint32_t& r0, uint32_t& r1,
                                       uint32_t& r2, uint32_t& r3, uint32_t a) {
    asm volatile("ldmatrix.sync.aligned.m8n8.x4.trans.shared.b16 {%0,%1,%2,%3}, [%4];"
                 : "=r"(r0), "=r"(r1), "=r"(r2), "=r"(r3) : "r"(a));
}
__device__ __forceinline__ void mma16816(float* c, const uint32_t* a,
                                         const uint32_t* b) {
    asm volatile(
        "mma.sync.aligned.m16n8k16.row.col.f32.bf16.bf16.f32 "
        "{%0,%1,%2,%3}, {%4,%5,%6,%7}, {%8,%9}, {%0,%1,%2,%3};"
        : "+f"(c[0]), "+f"(c[1]), "+f"(c[2]), "+f"(c[3])
        : "r"(a[0]), "r"(a[1]), "r"(a[2]), "r"(a[3]), "r"(b[0]), "r"(b[1]));
}
__device__ __forceinline__ uint32_t packbf(float a, float b) {
    __nv_bfloat162 p = __floats2bfloat162_rn(a, b);
    return *(uint32_t*)&p;
}

// ---------------------------------------------------------------------------
// Device-global scratch (allocation-free)
// ---------------------------------------------------------------------------
__device__ float g_xn  [NTOK_ * D_];
__device__ float g_xmid[NTOK_ * D_];
__device__ float g_xn2 [NTOK_ * D_];
__device__ float g_ya  [NTS_  * D_];
__device__ float g_yf  [NTS_  * D_];
__device__ float g_gwa [NTS_];
__device__ float g_gwf [NTS_];
__device__ int   g_cnt_a [EA_];
__device__ int   g_cnt_f [EF_];
__device__ int   g_cnt_id[2];
__device__ int   g_list_a[EA_ * CAP_];
__device__ int   g_list_f[EF_ * CAP_];
__device__ int   g_list_id[2 * CAP_];
__device__ float g_kvb [2 * HD_];           // packed k_b, v_b
// bf16 shadows / activations for tensor-core GEMMs
__device__ __nv_bfloat16 g_xn_bf [NTOK_ * D_];
__device__ __nv_bfloat16 g_xn2_bf[NTOK_ * D_];
__device__ __nv_bfloat16 g_q_bf  [NTS_  * HD_];
__device__ __nv_bfloat16 g_kv_bf [2 * NTOK_ * HD_]; // [0]=K, [1]=V
__device__ __nv_bfloat16 g_ctx_bf[NTS_  * HD_];
__device__ __nv_bfloat16 g_h_bf  [NTS_  * FH_];
__device__ __nv_bfloat16 g_w1t   [EF_ * FH_ * D_];   // [e][n=FH][k=D]
__device__ __nv_bfloat16 g_w2t   [EF_ * D_ * FH_];   // [e][n=D][k=FH]
__device__ __nv_bfloat16 g_qwt   [EA_ * HD_ * D_];   // [e][n=HD][k=D]
__device__ __nv_bfloat16 g_owt   [EA_ * D_ * HD_];   // [e][n=D][k=HD]
__device__ __nv_bfloat16 g_kvwt  [2 * HD_ * D_];     // [kv][n=HD][k=D]

// ---------------------------------------------------------------------------
// Setup: zero counters, identity list, packed kv bias
// ---------------------------------------------------------------------------
__global__ void __launch_bounds__(256) setup_k(const float* __restrict__ kb,
                                               const float* __restrict__ vb) {
    int i = blockIdx.x * 256 + threadIdx.x;
    if (i < EA_) g_cnt_a[i] = 0;
    if (i < EF_) g_cnt_f[i] = 0;
    if (i < 2)   g_cnt_id[i] = NTOK_;
    if (i < 2 * CAP_) g_list_id[i] = i & (CAP_ - 1);
    if (i < HD_) g_kvb[i] = kb[i];
    else if (i < 2 * HD_) g_kvb[i] = vb[i - HD_];
}

// ---------------------------------------------------------------------------
// Weight transpose + fp32->bf16 convert: W[E][K][N] -> O[E][N][K]
// ---------------------------------------------------------------------------
template<int K, int N>
__global__ void __launch_bounds__(256) convT_k(const float* __restrict__ W,
                                               __nv_bfloat16* __restrict__ O) {
    __shared__ float t[32][33];
    int e = blockIdx.z;
    int k0 = blockIdx.y * 32, n0 = blockIdx.x * 32;
    const float* w = W + (size_t)e * K * N;
    __nv_bfloat16* o = O + (size_t)e * N * K;
    int tx = threadIdx.x & 31, ty = threadIdx.x >> 5;
    #pragma unroll
    for (int i = 0; i < 32; i += 8)
        t[ty + i][tx] = w[(size_t)(k0 + ty + i) * N + n0 + tx];
    __syncthreads();
    #pragma unroll
    for (int i = 0; i < 32; i += 8)
        o[(size_t)(n0 + ty + i) * K + k0 + tx] = __float2bfloat16(t[tx][ty + i]);
}

// ---------------------------------------------------------------------------
// LayerNorm 1 (fp32 out + bf16 shadow)
// ---------------------------------------------------------------------------
__global__ void __launch_bounds__(256) ln1_k(
    const float* __restrict__ x, const float* __restrict__ w,
    const float* __restrict__ b, float* __restrict__ y,
    __nv_bfloat16* __restrict__ ybf)
{
    int t = blockIdx.x, tid = threadIdx.x;
    float4 v = ((const float4*)(x + (size_t)t * D_))[tid];
    float s = v.x + v.y + v.z + v.w;
    float q = fmaf(v.x, v.x, fmaf(v.y, v.y, fmaf(v.z, v.z, v.w * v.w)));
    __shared__ float ss[8], sq[8];
    #pragma unroll
    for (int o = 16; o; o >>= 1) {
        s += __shfl_xor_sync(0xffffffffu, s, o);
        q += __shfl_xor_sync(0xffffffffu, q, o);
    }
    if ((tid & 31) == 0) { ss[tid >> 5] = s; sq[tid >> 5] = q; }
    __syncthreads();
    if (tid == 0) {
        float a = 0.f, c = 0.f;
        #pragma unroll
        for (int i = 0; i < 8; i++) { a += ss[i]; c += sq[i]; }
        ss[0] = a; sq[0] = c;
    }
    __syncthreads();
    float mu  = ss[0] * (1.f / D_);
    float var = sq[0] * (1.f / D_) - mu * mu;
    float rs  = rsqrtf(var + 1e-5f);
    float4 wv = ((const float4*)w)[tid];
    float4 bv = ((const float4*)b)[tid];
    float4 o;
    o.x = (v.x - mu) * rs * wv.x + bv.x;
    o.y = (v.y - mu) * rs * wv.y + bv.y;
    o.z = (v.z - mu) * rs * wv.z + bv.z;
    o.w = (v.w - mu) * rs * wv.w + bv.w;
    ((float4*)(y + (size_t)t * D_))[tid] = o;
    uint2 st;
    st.x = packbf(o.x, o.y); st.y = packbf(o.z, o.w);
    *(uint2*)(ybf + (size_t)t * D_ + tid * 4) = st;
}

// Residual-add of two slot rows + LayerNorm fused
__global__ void __launch_bounds__(256) combine_ln2_k(
    const float* __restrict__ src, const float* __restrict__ ya,
    const float* __restrict__ w, const float* __restrict__ b,
    float* __restrict__ xmid, float* __restrict__ xn2,
    __nv_bfloat16* __restrict__ xn2bf)
{
    int t = blockIdx.x, tid = threadIdx.x;
    float4 v  = ((const float4*)(src + (size_t)t * D_))[tid];
    float4 y0 = ((const float4*)(ya + (size_t)(2 * t) * D_))[tid];
    float4 y1 = ((const float4*)(ya + (size_t)(2 * t + 1) * D_))[tid];
    v.x += y0.x + y1.x; v.y += y0.y + y1.y;
    v.z += y0.z + y1.z; v.w += y0.w + y1.w;
    ((float4*)(xmid + (size_t)t * D_))[tid] = v;

    float s = v.x + v.y + v.z + v.w;
    float q = fmaf(v.x, v.x, fmaf(v.y, v.y, fmaf(v.z, v.z, v.w * v.w)));
    __shared__ float ss[8], sq[8];
    #pragma unroll
    for (int o = 16; o; o >>= 1) {
        s += __shfl_xor_sync(0xffffffffu, s, o);
        q += __shfl_xor_sync(0xffffffffu, q, o);
    }
    if ((tid & 31) == 0) { ss[tid >> 5] = s; sq[tid >> 5] = q; }
    __syncthreads();
    if (tid == 0) {
        float a = 0.f, c = 0.f;
        #pragma unroll
        for (int i = 0; i < 8; i++) { a += ss[i]; c += sq[i]; }
        ss[0] = a; sq[0] = c;
    }
    __syncthreads();
    float mu  = ss[0] * (1.f / D_);
    float var = sq[0] * (1.f / D_) - mu * mu;
    float rs  = rsqrtf(var + 1e-5f);
    float4 wv = ((const float4*)w)[tid];
    float4 bv = ((const float4*)b)[tid];
    float4 o;
    o.x = (v.x - mu) * rs * wv.x + bv.x;
    o.y = (v.y - mu) * rs * wv.y + bv.y;
    o.z = (v.z - mu) * rs * wv.z + bv.z;
    o.w = (v.w - mu) * rs * wv.w + bv.w;
    ((float4*)(xn2 + (size_t)t * D_))[tid] = o;
    uint2 st;
    st.x = packbf(o.x, o.y); st.y = packbf(o.z, o.w);
    *(uint2*)(xn2bf + (size_t)t * D_ + tid * 4) = st;
}

// out = xmid + yf[2t] + yf[2t+1]
__global__ void __launch_bounds__(256) final_k(
    const float* __restrict__ xmid, const float* __restrict__ yf,
    float* __restrict__ out)
{
    int t = blockIdx.x, tid = threadIdx.x;
    float4 v  = ((const float4*)(xmid + (size_t)t * D_))[tid];
    float4 y0 = ((const float4*)(yf + (size_t)(2 * t) * D_))[tid];
    float4 y1 = ((const float4*)(yf + (size_t)(2 * t + 1) * D_))[tid];
    v.x += y0.x + y1.x; v.y += y0.y + y1.y;
    v.z += y0.z + y1.z; v.w += y0.w + y1.w;
    ((float4*)(out + (size_t)t * D_))[tid] = v;
}

// ---------------------------------------------------------------------------
// Routers (one warp per token, top-2, atomic list append)
// ---------------------------------------------------------------------------
__global__ void __launch_bounds__(256) route_attn_k(
    const float* __restrict__ xn, const float* __restrict__ gwm)
{
    int t = blockIdx.x * 8 + (threadIdx.x >> 5);
    int lane = threadIdx.x & 31;
    const float* x = xn + (size_t)t * D_;
    float acc[EA_];
    #pragma unroll
    for (int e = 0; e < EA_; e++) acc[e] = 0.f;
    for (int d = lane; d < D_; d += 32) {
        float xv = x[d];
        const float4* g4 = (const float4*)(gwm + (size_t)d * EA_);
        float4 ga = g4[0], gb = g4[1];
        acc[0] = fmaf(xv, ga.x, acc[0]); acc[1] = fmaf(xv, ga.y, acc[1]);
        acc[2] = fmaf(xv, ga.z, acc[2]); acc[3] = fmaf(xv, ga.w, acc[3]);
        acc[4] = fmaf(xv, gb.x, acc[4]); acc[5] = fmaf(xv, gb.y, acc[5]);
        acc[6] = fmaf(xv, gb.z, acc[6]); acc[7] = fmaf(xv, gb.w, acc[7]);
    }
    #pragma unroll
    for (int e = 0; e < EA_; e++)
        #pragma unroll
        for (int o = 16; o; o >>= 1)
            acc[e] += __shfl_xor_sync(0xffffffffu, acc[e], o);
    if (lane == 0) {
        int i0 = 0; float v0 = acc[0];
        #pragma unroll
        for (int e = 1; e < EA_; e++) if (acc[e] > v0) { v0 = acc[e]; i0 = e; }
        int i1 = -1; float v1 = -1e30f;
        #pragma unroll
        for (int e = 0; e < EA_; e++)
            if (e != i0 && acc[e] > v1) { v1 = acc[e]; i1 = e; }
        float e1 = __expf(v1 - v0);
        float inv = 1.f / (1.f + e1);
        g_gwa[2 * t]     = inv;
        g_gwa[2 * t + 1] = e1 * inv;
        int p0 = atomicAdd(&g_cnt_a[i0], 1);
        g_list_a[i0 * CAP_ + p0] = 2 * t;
        int p1 = atomicAdd(&g_cnt_a[i1], 1);
        g_list_a[i1 * CAP_ + p1] = 2 * t + 1;
    }
}

__global__ void __launch_bounds__(256) route_ffn_k(
    const float* __restrict__ xn, const float* __restrict__ gwm)
{
    int t = blockIdx.x * 8 + (threadIdx.x >> 5);
    int lane = threadIdx.x & 31;
    const float* x = xn + (size_t)t * D_;
    float acc[EF_];
    #pragma unroll
    for (int e = 0; e < EF_; e++) acc[e] = 0.f;
    for (int d = lane; d < D_; d += 32) {
        float xv = x[d];
        const float4* g4 = (const float4*)(gwm + (size_t)d * EF_);
        #pragma unroll
        for (int g = 0; g < 4; g++) {
            float4 gv = g4[g];
            acc[g*4+0] = fmaf(xv, gv.x, acc[g*4+0]);
            acc[g*4+1] = fmaf(xv, gv.y, acc[g*4+1]);
            acc[g*4+2] = fmaf(xv, gv.z, acc[g*4+2]);
            acc[g*4+3] = fmaf(xv, gv.w, acc[g*4+3]);
        }
    }
    #pragma unroll
    for (int e = 0; e < EF_; e++)
        #pragma unroll
        for (int o = 16; o; o >>= 1)
            acc[e] += __shfl_xor_sync(0xffffffffu, acc[e], o);
    if (lane == 0) {
        int i0 = 0; float v0 = acc[0];
        #pragma unroll
        for (int e = 1; e < EF_; e++) if (acc[e] > v0) { v0 = acc[e]; i0 = e; }
        int i1 = -1; float v1 = -1e30f;
        #pragma unroll
        for (int e = 0; e < EF_; e++)
            if (e != i0 && acc[e] > v1) { v1 = acc[e]; i1 = e; }
        float e1 = __expf(v1 - v0);
        float inv = 1.f / (1.f + e1);
        g_gwf[2 * t]     = inv;
        g_gwf[2 * t + 1] = e1 * inv;
        int p0 = atomicAdd(&g_cnt_f[i0], 1);
        g_list_f[i0 * CAP_ + p0] = 2 * t;
        int p1 = atomicAdd(&g_cnt_f[i1], 1);
        g_list_f[i1 * CAP_ + p1] = 2 * t + 1;
    }
}

// ---------------------------------------------------------------------------
// bf16 mma.sync grouped/gather GEMM (all projections + FFN).
// ---------------------------------------------------------------------------
#define LDAB 72   // bf16 elements per smem row (64 + 8 pad): 144B stride

template<int KTOT, bool TOKROW, bool RELU, bool GATE, bool OUTBF>
__global__ void __launch_bounds__(256) mmasync_gemm_k(
    const __nv_bfloat16* __restrict__ Abase,
    const __nv_bfloat16* __restrict__ Bbase,
    const float* __restrict__ biasb, int Nfull,
    void* __restrict__ Yv, int ldy, size_t eStrideY,
    const int* __restrict__ lists, const int* __restrict__ cnts,
    const float* __restrict__ gw, float scale)
{
    int e = blockIdx.z;
    int cnt = cnts[e];
    int row0 = blockIdx.y * 128;
    if (row0 >= cnt) return;
    int n0 = blockIdx.x * 128;
    const int* list = lists + e * CAP_;

    __shared__ __nv_bfloat16 As[128 * LDAB];
    __shared__ __nv_bfloat16 Bs[128 * LDAB];
    __shared__ float bias_s[128];
    __shared__ float gate_s[128];
    __shared__ int   slot_s[128];

    int tid = threadIdx.x;
    int wid = tid >> 5, lane = tid & 31;

    if (tid < 128) {
        int r = min(row0 + tid, cnt - 1);
        int sl = list[r];
        slot_s[tid] = sl;
        gate_s[tid] = GATE ? gw[sl] : 1.f;
        bias_s[tid] = biasb[(size_t)e * Nfull + n0 + tid];
    }

    const __nv_bfloat16* Bexp = Bbase + (size_t)e * Nfull * KTOT;
    const __nv_bfloat16* aSrc[4];
    const __nv_bfloat16* bSrc[4];
    uint32_t aDst[4], bDst[4];
    uint32_t sA = smem_to_u32(As), sB = smem_to_u32(Bs);
    #pragma unroll
    for (int i = 0; i < 4; i++) {
        int idx = tid + i * 256;
        int m = idx >> 3, c = idx & 7;
        int r = min(row0 + m, cnt - 1);
        int sl = list[r];
        int gr = TOKROW ? (sl >> 1) : sl;
        aSrc[i] = Abase + (size_t)gr * KTOT + c * 8;
        bSrc[i] = Bexp + (size_t)(n0 + m) * KTOT + c * 8;
        aDst[i] = sA + (m * LDAB + c * 8) * 2;
        bDst[i] = sB + (m * LDAB + c * 8) * 2;
    }

    int warpM = (wid & 3) * 32;
    int warpN = (wid >> 2) * 64;
    uint32_t aAddr = sA + ((warpM + (lane & 15)) * LDAB + (lane >> 4) * 8) * 2;
    uint32_t bAddr = sB + ((warpN + ((lane >> 4) & 1) * 8 + (lane & 7)) * LDAB
                           + ((lane >> 3) & 1) * 8) * 2;

    float acc[2][8][4];
    #pragma unroll
    for (int mt = 0; mt < 2; mt++)
        #pragma unroll
        for (int nt = 0; nt < 8; nt++)
            #pragma unroll
            for (int j = 0; j < 4; j++) acc[mt][nt][j] = 0.f;

    uint4 aR[4], bR[4];
    #pragma unroll
    for (int i = 0; i < 4; i++) {
        aR[i] = *(const uint4*)(aSrc[i]);
        bR[i] = *(const uint4*)(bSrc[i]);
    }

    const int NSTAGE = KTOT / 64;
    for (int st = 0; st < NSTAGE; st++) {
        __syncthreads();
        #pragma unroll
        for (int i = 0; i < 4; i++) {
            asm volatile("st.shared.v4.b32 [%0], {%1,%2,%3,%4};" ::
                "r"(aDst[i]), "r"(aR[i].x), "r"(aR[i].y), "r"(aR[i].z), "r"(aR[i].w));
            asm volatile("st.shared.v4.b32 [%0], {%1,%2,%3,%4};" ::
                "r"(bDst[i]), "r"(bR[i].x), "r"(bR[i].y), "r"(bR[i].z), "r"(bR[i].w));
        }
        __syncthreads();
        if (st + 1 < NSTAGE) {
            int k0 = (st + 1) * 64;
            #pragma unroll
            for (int i = 0; i < 4; i++) {
                aR[i] = *(const uint4*)(aSrc[i] + k0);
                bR[i] = *(const uint4*)(bSrc[i] + k0);
            }
        }
        #pragma unroll
        for (int kk = 0; kk < 4; kk++) {
            uint32_t a[2][4];
            ldsm4(a[0][0], a[0][1], a[0][2], a[0][3], aAddr + kk * 32);
            ldsm4(a[1][0], a[1][1], a[1][2], a[1][3],
                  aAddr + 16 * LDAB * 2 + kk * 32);
            uint32_t b[8][2];
            #pragma unroll
            for (int nt2 = 0; nt2 < 4; nt2++) {
                uint32_t r0, r1, r2, r3;
                ldsm4(r0, r1, r2, r3, bAddr + nt2 * 16 * LDAB * 2 + kk * 32);
                b[nt2 * 2][0] = r0;     b[nt2 * 2][1] = r1;
                b[nt2 * 2 + 1][0] = r2; b[nt2 * 2 + 1][1] = r3;
            }
            #pragma unroll
            for (int mt = 0; mt < 2; mt++)
                #pragma unroll
                for (int nt = 0; nt < 8; nt++)
                    mma16816(acc[mt][nt], a[mt], b[nt]);
        }
    }

    int lane4 = lane >> 2;
    int lcol  = (lane & 3) * 2;
    #pragma unroll
    for (int mt = 0; mt < 2; mt++) {
        #pragma unroll
        for (int h = 0; h < 2; h++) {
            int m = warpM + mt * 16 + lane4 + h * 8;
            if (row0 + m >= cnt) continue;
            int sl = slot_s[m];
            float f = gate_s[m];
            size_t ybase = (size_t)e * eStrideY + (size_t)sl * ldy + n0;
            #pragma unroll
            for (int nt = 0; nt < 8; nt++) {
                int col = warpN + nt * 8 + lcol;
                float v0 = (acc[mt][nt][h * 2 + 0] + bias_s[col]) * scale;
                float v1 = (acc[mt][nt][h * 2 + 1] + bias_s[col + 1]) * scale;
                if (RELU) { v0 = fmaxf(v0, 0.f); v1 = fmaxf(v1, 0.f); }
                v0 *= f; v1 *= f;
                if (OUTBF) {
                    *(uint32_t*)((__nv_bfloat16*)Yv + ybase + col) = packbf(v0, v1);
                } else {
                    float2 p = make_float2(v0, v1);
                    *(float2*)((float*)Yv + ybase + col) = p;
                }
            }
        }
    }
}

// ---------------------------------------------------------------------------
// Tensor-core flash attention.
// Block = 64 slots. 8 warps = 2 key-groups (wg) x 4 warps; warp owns 16 rows.
// wg w processes key tiles 2t+w (64 keys each); independent online softmax;
// merged at the end. Rel-pos scores precomputed per block via mma.
// smem layout (bytes):
//   Qs  bf16[64][136]      @ 0       (17408)
//   Ks  bf16[2][64][136]   @ 17408   (34816)
//   Vs  bf16[2][64][136]   @ 52224   (34816)
//   Rl  f32 [64][132]      @ 87040   (33792)   (reused for ctx merge)
//   sM  f32 [2][64]        @ 120832  (512)
//   sL  f32 [2][64]        @ 121344  (512)
// ---------------------------------------------------------------------------
#define ATT2_QS   0
#define ATT2_KS   17408
#define ATT2_VS   52224
#define ATT2_RL   87040
#define ATT2_SM   120832
#define ATT2_SL   121344
#define ATT2_SMEM 121856

__global__ void __launch_bounds__(256) attn_mma_k(
    const __nv_bfloat16* __restrict__ qg,
    const __nv_bfloat16* __restrict__ kg,
    const __nv_bfloat16* __restrict__ vg,
    const float* __restrict__ rel,
    __nv_bfloat16* __restrict__ ctxg)
{
    extern __shared__ char smraw[];
    __nv_bfloat16* Qs = (__nv_bfloat16*)(smraw + ATT2_QS);
    float* Rl = (float*)(smraw + ATT2_RL);
    float* sM = (float*)(smraw + ATT2_SM);
    float* sL = (float*)(smraw + ATT2_SL);

    int tid = threadIdx.x;
    int wid = tid >> 5, lane = tid & 31;
    int wg = wid >> 2, ww = wid & 3;
    int t128 = tid & 127;

    int gs0 = blockIdx.x * 64;      // global slot base
    int b   = gs0 >> 11;            // batch
    int ls0 = gs0 & 2047;           // slot base within batch

    // ---- load Q[64][128] bf16 ----
    {
        int r = tid >> 2, cb = (tid & 3) * 32;
        const uint4* src = (const uint4*)(qg + (size_t)(gs0 + r) * HD_ + cb);
        uint4* dst = (uint4*)(smraw + ATT2_QS + r * 272 + cb * 2);
        #pragma unroll
        for (int i = 0; i < 4; i++) dst[i] = src[i];
    }
    // ---- load rel tiles (fp32 -> bf16): wg w loads rel rows w*64..w*64+63 ----
    {
        int r = t128 >> 1, cb = (t128 & 1) * 64;
        int rr = wg * 64 + r;   // 0..127, all valid (rel has 129 rows)
        const float* src = rel + (size_t)rr * HD_ + cb;
        char* dst = smraw + ATT2_KS + wg * (64 * 272) + r * 272 + cb * 2;
        #pragma unroll
        for (int i = 0; i < 8; i++) {
            float4 f0 = *(const float4*)(src + i * 8);
            float4 f1 = *(const float4*)(src + i * 8 + 4);
            uint4 st;
            st.x = packbf(f0.x, f0.y); st.y = packbf(f0.z, f0.w);
            st.z = packbf(f1.x, f1.y); st.w = packbf(f1.z, f1.w);
            *(uint4*)(dst + i * 16) = st;
        }
    }
    __syncthreads();

    // ---- preload Q fragments (warp rows ww*16..+15) ----
    uint32_t sQ = smem_to_u32(smraw + ATT2_QS);
    uint32_t aQAddr = sQ + (ww * 16 + (lane & 15)) * 272 + (lane >> 4) * 16;
    uint32_t qf[8][4];
    #pragma unroll
    for (int ks = 0; ks < 8; ks++)
        ldsm4(qf[ks][0], qf[ks][1], qf[ks][2], qf[ks][3], aQAddr + ks * 32);

    int bRow = ((lane >> 4) & 1) * 8 + (lane & 7);
    int bColB = ((lane >> 3) & 1) * 16;
    uint32_t sKw = smem_to_u32(smraw + ATT2_KS) + wg * (64 * 272);
    uint32_t sVw = smem_to_u32(smraw + ATT2_VS) + wg * (64 * 272);

    int r0 = lane >> 2, cA = (lane & 3) * 2;
    int m0row = ww * 16 + r0;

    // ---- rel scores via mma: Rl[m][wg*64 + j] = q[m] . rel[wg*64+j] ----
    {
        float c[8][4];
        #pragma unroll
        for (int nt = 0; nt < 8; nt++)
            #pragma unroll
            for (int j = 0; j < 4; j++) c[nt][j] = 0.f;
        #pragma unroll
        for (int ks = 0; ks < 8; ks++) {
            uint32_t bfd[8][2];
            #pragma unroll
            for (int np = 0; np < 4; np++) {
                uint32_t x0, x1, x2, x3;
                ldsm4(x0, x1, x2, x3,
                      sKw + (np * 16 + bRow) * 272 + bColB + ks * 32);
                bfd[np * 2][0] = x0;     bfd[np * 2][1] = x1;
                bfd[np * 2 + 1][0] = x2; bfd[np * 2 + 1][1] = x3;
            }
            #pragma unroll
            for (int nt = 0; nt < 8; nt++)
                mma16816(c[nt], qf[ks], bfd[nt]);
        }
        #pragma unroll
        for (int nt = 0; nt < 8; nt++) {
            int col = wg * 64 + nt * 8 + cA;
            Rl[m0row * 132 + col]           = c[nt][0];
            Rl[m0row * 132 + col + 1]       = c[nt][1];
            Rl[(m0row + 8) * 132 + col]     = c[nt][2];
            Rl[(m0row + 8) * 132 + col + 1] = c[nt][3];
        }
    }
    // rel col 128 (row 128 of rel table), scalar
    {
        int m = tid >> 2, l4 = tid & 3;
        const float* rrow = rel + (size_t)128 * HD_ + l4 * 32;
        const __nv_bfloat16* qrow = Qs + m * 136 + l4 * 32;
        float s = 0.f;
        #pragma unroll
        for (int i = 0; i < 32; i++)
            s = fmaf(__bfloat162float(qrow[i]), rrow[i], s);
        s += __shfl_xor_sync(0xffffffffu, s, 1);
        s += __shfl_xor_sync(0xffffffffu, s, 2);
        if (l4 == 0) Rl[m * 132 + 128] = s;
    }
    __syncthreads();

    // ---- main loop over key tiles ----
    float m_run0 = -1e30f, m_run1 = -1e30f;
    float l_run0 = 0.f, l_run1 = 0.f;
    float ctx[16][4];
    #pragma unroll
    for (int nt = 0; nt < 16; nt++)
        #pragma unroll
        for (int j = 0; j < 4; j++) ctx[nt][j] = 0.f;

    int pos0 = (ls0 + m0row) >> 1;
    int pos1 = (ls0 + m0row + 8) >> 1;
    int vRow = lane & 15;
    int vColB = (lane >> 4) * 16;

    for (int t = 0; t < 8; t++) {
        int kt = t * 2 + wg;
        int j0 = kt * 64;
        // load K/V tile (128 threads of this wg)
        {
            int r = t128 >> 1, cb = (t128 & 1) * 64;
            const uint4* ksrc = (const uint4*)(kg + (size_t)(b * S_ + j0 + r) * HD_ + cb);
            const uint4* vsrc = (const uint4*)(vg + (size_t)(b * S_ + j0 + r) * HD_ + cb);
            uint4* kd = (uint4*)(smraw + ATT2_KS + wg * (64 * 272) + r * 272 + cb * 2);
            uint4* vd = (uint4*)(smraw + ATT2_VS + wg * (64 * 272) + r * 272 + cb * 2);
            #pragma unroll
            for (int i = 0; i < 8; i++) { kd[i] = ksrc[i]; vd[i] = vsrc[i]; }
        }
        __syncthreads();

        // scores S[16][64]
        float c[8][4];
        #pragma unroll
        for (int nt = 0; nt < 8; nt++)
            #pragma unroll
            for (int j = 0; j < 4; j++) c[nt][j] = 0.f;
        #pragma unroll
        for (int ks = 0; ks < 8; ks++) {
            uint32_t bfd[8][2];
            #pragma unroll
            for (int np = 0; np < 4; np++) {
                uint32_t x0, x1, x2, x3;
                ldsm4(x0, x1, x2, x3,
                      sKw + (np * 16 + bRow) * 272 + bColB + ks * 32);
                bfd[np * 2][0] = x0;     bfd[np * 2][1] = x1;
                bfd[np * 2 + 1][0] = x2; bfd[np * 2 + 1][1] = x3;
            }
            #pragma unroll
            for (int nt = 0; nt < 8; nt++)
                mma16816(c[nt], qf[ks], bfd[nt]);
        }
        // + rel scores (Shaw)
        #pragma unroll
        for (int nt = 0; nt < 8; nt++) {
            int j = j0 + nt * 8 + cA;
            int i00 = min(max(j - pos0, -64), 64) + 64;
            int i01 = min(max(j + 1 - pos0, -64), 64) + 64;
            int i10 = min(max(j - pos1, -64), 64) + 64;
            int i11 = min(max(j + 1 - pos1, -64), 64) + 64;
            c[nt][0] += Rl[m0row * 132 + i00];
            c[nt][1] += Rl[m0row * 132 + i01];
            c[nt][2] += Rl[(m0row + 8) * 132 + i10];
            c[nt][3] += Rl[(m0row + 8) * 132 + i11];
        }
        // online softmax (rows fully within quad)
        float mx0 = -1e30f, mx1 = -1e30f;
        #pragma unroll
        for (int nt = 0; nt < 8; nt++) {
            mx0 = fmaxf(mx0, fmaxf(c[nt][0], c[nt][1]));
            mx1 = fmaxf(mx1, fmaxf(c[nt][2], c[nt][3]));
        }
        mx0 = fmaxf(mx0, __shfl_xor_sync(0xffffffffu, mx0, 1));
        mx0 = fmaxf(mx0, __shfl_xor_sync(0xffffffffu, mx0, 2));
        mx1 = fmaxf(mx1, __shfl_xor_sync(0xffffffffu, mx1, 1));
        mx1 = fmaxf(mx1, __shfl_xor_sync(0xffffffffu, mx1, 2));
        float mn0 = fmaxf(m_run0, mx0), mn1 = fmaxf(m_run1, mx1);
        float sc0 = __expf(m_run0 - mn0), sc1 = __expf(m_run1 - mn1);
        m_run0 = mn0; m_run1 = mn1;
        float rs0 = 0.f, rs1 = 0.f;
        #pragma unroll
        for (int nt = 0; nt < 8; nt++) {
            c[nt][0] = __expf(c[nt][0] - mn0); rs0 += c[nt][0];
            c[nt][1] = __expf(c[nt][1] - mn0); rs0 += c[nt][1];
            c[nt][2] = __expf(c[nt][2] - mn1); rs1 += c[nt][2];
            c[nt][3] = __expf(c[nt][3] - mn1); rs1 += c[nt][3];
        }
        rs0 += __shfl_xor_sync(0xffffffffu, rs0, 1);
        rs0 += __shfl_xor_sync(0xffffffffu, rs0, 2);
        rs1 += __shfl_xor_sync(0xffffffffu, rs1, 1);
        rs1 += __shfl_xor_sync(0xffffffffu, rs1, 2);
        l_run0 = l_run0 * sc0 + rs0;
        l_run1 = l_run1 * sc1 + rs1;
        #pragma unroll
        for (int nt = 0; nt < 16; nt++) {
            ctx[nt][0] *= sc0; ctx[nt][1] *= sc0;
            ctx[nt][2] *= sc1; ctx[nt][3] *= sc1;
        }
        // pack P -> A fragments (C frag of S maps 1:1 to A frag halves)
        uint32_t pf[4][4];
        #pragma unroll
        for (int k2 = 0; k2 < 4; k2++) {
            pf[k2][0] = packbf(c[2 * k2][0], c[2 * k2][1]);
            pf[k2][1] = packbf(c[2 * k2][2], c[2 * k2][3]);
            pf[k2][2] = packbf(c[2 * k2 + 1][0], c[2 * k2 + 1][1]);
            pf[k2][3] = packbf(c[2 * k2 + 1][2], c[2 * k2 + 1][3]);
        }
        // PV: ctx[16 n-tiles of dims] += P[16][64] @ V[64][128]
        #pragma unroll
        for (int k2 = 0; k2 < 4; k2++) {
            #pragma unroll
            for (int dp = 0; dp < 8; dp++) {
                uint32_t x0, x1, x2, x3;
                ldsm4t(x0, x1, x2, x3,
                       sVw + (k2 * 16 + vRow) * 272 + dp * 32 + vColB);
                uint32_t b0[2] = {x0, x1};
                uint32_t b1[2] = {x2, x3};
                mma16816(ctx[2 * dp], pf[k2], b0);
                mma16816(ctx[2 * dp + 1], pf[k2], b1);
            }
        }
        __syncthreads();
    }

    // ---- merge the two key-groups ----
    if ((lane & 3) == 0) {
        sM[wg * 64 + m0row] = m_run0;     sL[wg * 64 + m0row] = l_run0;
        sM[wg * 64 + m0row + 8] = m_run1; sL[wg * 64 + m0row + 8] = l_run1;
    }
    __syncthreads();
    float mo0 = sM[(1 - wg) * 64 + m0row];
    float mo1 = sM[(1 - wg) * 64 + m0row + 8];
    float lo0 = sL[(1 - wg) * 64 + m0row];
    float lo1 = sL[(1 - wg) * 64 + m0row + 8];
    float M0 = fmaxf(m_run0, mo0), M1 = fmaxf(m_run1, mo1);
    float s0 = __expf(m_run0 - M0), s1 = __expf(m_run1 - M1);
    float lt0 = l_run0 * s0 + lo0 * __expf(mo0 - M0);
    float lt1 = l_run1 * s1 + lo1 * __expf(mo1 - M1);
    #pragma unroll
    for (int nt = 0; nt < 16; nt++) {
        ctx[nt][0] *= s0; ctx[nt][1] *= s0;
        ctx[nt][2] *= s1; ctx[nt][3] *= s1;
    }
    __syncthreads();   // Rl free for reuse as merge buffer
    if (wg == 1) {
        #pragma unroll
        for (int nt = 0; nt < 16; nt++) {
            int col = nt * 8 + cA;
            Rl[m0row * 132 + col]           = ctx[nt][0];
            Rl[m0row * 132 + col + 1]       = ctx[nt][1];
            Rl[(m0row + 8) * 132 + col]     = ctx[nt][2];
            Rl[(m0row + 8) * 132 + col + 1] = ctx[nt][3];
        }
    }
    __syncthreads();
    if (wg == 0) {
        float inv0 = 1.f / lt0, inv1 = 1.f / lt1;
        #pragma unroll
        for (int nt = 0; nt < 16; nt++) {
            int col = nt * 8 + cA;
            float v0 = (ctx[nt][0] + Rl[m0row * 132 + col]) * inv0;
            float v1 = (ctx[nt][1] + Rl[m0row * 132 + col + 1]) * inv0;
            float v2 = (ctx[nt][2] + Rl[(m0row + 8) * 132 + col]) * inv1;
            float v3 = (ctx[nt][3] + Rl[(m0row + 8) * 132 + col + 1]) * inv1;
            *(uint32_t*)(ctxg + (size_t)(gs0 + m0row) * HD_ + col) = packbf(v0, v1);
            *(uint32_t*)(ctxg + (size_t)(gs0 + m0row + 8) * HD_ + col) = packbf(v2, v3);
        }
    }
}

// ---------------------------------------------------------------------------
// Host launcher
// ---------------------------------------------------------------------------
extern "C" void kernel_launch(void* const* d_in, const int* in_sizes, int n_in,
                              void* d_out, int out_size) {
    const float* src  = (const float*)d_in[0];
    const float* ln1w = (const float*)d_in[1];
    const float* ln1b = (const float*)d_in[2];
    const float* ln2w = (const float*)d_in[3];
    const float* ln2b = (const float*)d_in[4];
    const float* agw  = (const float*)d_in[5];
    const float* qw   = (const float*)d_in[6];
    const float* qb   = (const float*)d_in[7];
    const float* kw   = (const float*)d_in[8];
    const float* kb   = (const float*)d_in[9];
    const float* vw   = (const float*)d_in[10];
    const float* vb   = (const float*)d_in[11];
    const float* ow   = (const float*)d_in[12];
    const float* ob   = (const float*)d_in[13];
    const float* rel  = (const float*)d_in[14];
    const float* fgw  = (const float*)d_in[15];
    const float* w1   = (const float*)d_in[16];
    const float* b1   = (const float*)d_in[17];
    const float* w2   = (const float*)d_in[18];
    const float* b2   = (const float*)d_in[19];
    float* out = (float*)d_out;

    float *xn, *xmid, *xn2, *ya, *yf, *gwa, *gwf, *kvb;
    int *cnta, *cntf, *cntid, *lista, *listf, *listid;
    __nv_bfloat16 *xnbf, *xn2bf, *qbf, *kvbf, *ctxbf, *hbf;
    __nv_bfloat16 *w1t, *w2t, *qwt, *owt, *kvwt;
    cudaGetSymbolAddress((void**)&xn,    g_xn);
    cudaGetSymbolAddress((void**)&xmid,  g_xmid);
    cudaGetSymbolAddress((void**)&xn2,   g_xn2);
    cudaGetSymbolAddress((void**)&ya,    g_ya);
    cudaGetSymbolAddress((void**)&yf,    g_yf);
    cudaGetSymbolAddress((void**)&gwa,   g_gwa);
    cudaGetSymbolAddress((void**)&gwf,   g_gwf);
    cudaGetSymbolAddress((void**)&kvb,   g_kvb);
    cudaGetSymbolAddress((void**)&cnta,  g_cnt_a);
    cudaGetSymbolAddress((void**)&cntf,  g_cnt_f);
    cudaGetSymbolAddress((void**)&cntid, g_cnt_id);
    cudaGetSymbolAddress((void**)&lista, g_list_a);
    cudaGetSymbolAddress((void**)&listf, g_list_f);
    cudaGetSymbolAddress((void**)&listid,g_list_id);
    cudaGetSymbolAddress((void**)&xnbf,  g_xn_bf);
    cudaGetSymbolAddress((void**)&xn2bf, g_xn2_bf);
    cudaGetSymbolAddress((void**)&qbf,   g_q_bf);
    cudaGetSymbolAddress((void**)&kvbf,  g_kv_bf);
    cudaGetSymbolAddress((void**)&ctxbf, g_ctx_bf);
    cudaGetSymbolAddress((void**)&hbf,   g_h_bf);
    cudaGetSymbolAddress((void**)&w1t,   g_w1t);
    cudaGetSymbolAddress((void**)&w2t,   g_w2t);
    cudaGetSymbolAddress((void**)&qwt,   g_qwt);
    cudaGetSymbolAddress((void**)&owt,   g_owt);
    cudaGetSymbolAddress((void**)&kvwt,  g_kvwt);

    static bool attr_set = []() {
        cudaFuncSetAttribute(attn_mma_k,
                             cudaFuncAttributeMaxDynamicSharedMemorySize,
                             ATT2_SMEM);
        return true;
    }();
    (void)attr_set;

    setup_k<<<(2 * CAP_) / 256, 256>>>(kb, vb);

    // bf16 transposed weight shadows
    convT_k<D_, FH_><<<dim3(FH_ / 32, D_ / 32, EF_), 256>>>(w1, w1t);
    convT_k<FH_, D_><<<dim3(D_ / 32, FH_ / 32, EF_), 256>>>(w2, w2t);
    convT_k<D_, HD_><<<dim3(HD_ / 32, D_ / 32, EA_), 256>>>(qw, qwt);
    convT_k<HD_, D_><<<dim3(D_ / 32, HD_ / 32, EA_), 256>>>(ow, owt);
    convT_k<D_, HD_><<<dim3(HD_ / 32, D_ / 32, 1), 256>>>(kw, kvwt);
    convT_k<D_, HD_><<<dim3(HD_ / 32, D_ / 32, 1), 256>>>(vw, kvwt + (size_t)HD_ * D_);

    ln1_k<<<NTOK_, 256>>>(src, ln1w, ln1b, xn, xnbf);

    // fused K/V projection -> bf16 ("experts" 0/1 over identity list)
    mmasync_gemm_k<D_, false, false, false, true>
        <<<dim3(1, NTOK_ / 128, 2), 256>>>(
        xnbf, kvwt, kvb, HD_, (void*)kvbf, HD_, (size_t)NTOK_ * HD_,
        listid, cntid, nullptr, 1.f);

    route_attn_k<<<NTOK_ / 8, 256>>>(xn, agw);

    // per-expert Q projection (gathered, scaled, bf16 out)
    mmasync_gemm_k<D_, true, false, false, true>
        <<<dim3(1, CAP_ / 128, EA_), 256>>>(
        xnbf, qwt, qb, HD_, (void*)qbf, HD_, 0,
        lista, cnta, nullptr, 0.08838834764831845f);

    // tensor-core flash attention
    attn_mma_k<<<NTS_ / 64, 256, ATT2_SMEM>>>(
        qbf, kvbf, kvbf + (size_t)NTOK_ * HD_, rel, ctxbf);

    // per-expert output projection, gated (K=128, fp32 out)
    mmasync_gemm_k<HD_, false, false, true, false>
        <<<dim3(D_ / 128, CAP_ / 128, EA_), 256>>>(
        ctxbf, owt, ob, D_, (void*)ya, D_, 0,
        lista, cnta, gwa, 1.f);

    combine_ln2_k<<<NTOK_, 256>>>(src, ya, ln2w, ln2b, xmid, xn2, xn2bf);
    route_ffn_k<<<NTOK_ / 8, 256>>>(xn2, fgw);

    // FFN via bf16 mma.sync
    mmasync_gemm_k<D_, true, true, false, true>
        <<<dim3(FH_ / 128, CAP_ / 128, EF_), 256>>>(
        xn2bf, w1t, b1, FH_, (void*)hbf, FH_, 0,
        listf, cntf, nullptr, 1.f);
    mmasync_gemm_k<FH_, false, false, true, false>
        <<<dim3(D_ / 128, CAP_ / 128, EF_), 256>>>(
        hbf, w2t, b2, D_, (void*)yf, D_, 0,
        listf, cntf, gwf, 1.f);

    final_k<<<NTOK_, 256>>>(xmid, yf, out);
}